// round 3
// baseline (speedup 1.0000x reference)
#include <cuda_runtime.h>
#include <cstddef>

#define T_STEPS 512
#define B_SZ    256
#define H_SZ    512
#define I_SZ    192
#define G4      2048   // 4*H

// Scratch (allocation-free rule: __device__ globals)
__device__ float g_xg[(size_t)T_STEPS * B_SZ * G4];   // [T][B][4H]  (1 GiB)
__device__ float g_h [2][(size_t)B_SZ * H_SZ];        // double-buffered hidden (4 MiB)
__device__ float g_c [(size_t)B_SZ * H_SZ];           // cell state (in-place per step)

// ---------------------------------------------------------------------------
// Kernel 0: seed output with bias (d_out is poisoned before timing)
// ---------------------------------------------------------------------------
__global__ void init_out_kernel(float* __restrict__ out, const float* __restrict__ b_out) {
    int i = blockIdx.x * blockDim.x + threadIdx.x;
    if (i < B_SZ * T_STEPS) out[i] = b_out[0];
}

// ---------------------------------------------------------------------------
// Kernel 1: xg[t][b][g] = concat(obs,act)[b,t,:] . W_ih[g,:] + b_ih[g] + b_hh[g]
// Tiled fp32 GEMM: M = B*T (131072), N = 4H (2048), K = I (192).
// Block tile 64x64, 256 threads, 4x4 register microtile.
// ---------------------------------------------------------------------------
__global__ void xg_kernel(const float* __restrict__ obs, const float* __restrict__ act,
                          const float* __restrict__ W_ih, const float* __restrict__ b_ih,
                          const float* __restrict__ b_hh) {
    __shared__ float aS[16][65]; // [kk][m] k-major, padded
    __shared__ float bS[16][65]; // [kk][n]
    const int m0  = blockIdx.y * 64;
    const int n0  = blockIdx.x * 64;
    const int tid = threadIdx.x;
    const int nIdx = tid & 15;   // n-lane (x4 strided)
    const int mIdx = tid >> 4;   // m-group (x4 contiguous)
    float acc[4][4] = {};

    for (int k0 = 0; k0 < I_SZ; k0 += 16) {
        #pragma unroll
        for (int i = 0; i < 4; i++) {
            int idx = tid + i * 256;
            int r = idx >> 4, kk = idx & 15;
            int m = m0 + r;
            int b = m >> 9, t = m & 511;
            int k = k0 + kk;
            float v;
            if (k < 128) v = obs[((size_t)(b * T_STEPS + t)) * 128 + k];
            else         v = act[((size_t)(b * T_STEPS + t)) * 64 + (k - 128)];
            aS[kk][r] = v;
        }
        #pragma unroll
        for (int i = 0; i < 4; i++) {
            int idx = tid + i * 256;
            int r = idx >> 4, kk = idx & 15;
            bS[kk][r] = W_ih[(size_t)(n0 + r) * I_SZ + (k0 + kk)];
        }
        __syncthreads();
        #pragma unroll
        for (int kk = 0; kk < 16; kk++) {
            float a[4], bv[4];
            #pragma unroll
            for (int ii = 0; ii < 4; ii++) a[ii] = aS[kk][mIdx * 4 + ii];
            #pragma unroll
            for (int jj = 0; jj < 4; jj++) bv[jj] = bS[kk][nIdx + 16 * jj];
            #pragma unroll
            for (int ii = 0; ii < 4; ii++)
                #pragma unroll
                for (int jj = 0; jj < 4; jj++)
                    acc[ii][jj] = fmaf(a[ii], bv[jj], acc[ii][jj]);
        }
        __syncthreads();
    }
    #pragma unroll
    for (int jj = 0; jj < 4; jj++) {
        int n = n0 + nIdx + 16 * jj;
        float bias = b_ih[n] + b_hh[n];
        #pragma unroll
        for (int ii = 0; ii < 4; ii++) {
            int m = m0 + mIdx * 4 + ii;
            int b = m >> 9, t = m & 511;
            g_xg[((size_t)t * B_SZ + b) * G4 + n] = acc[ii][jj] + bias;
        }
    }
}

// ---------------------------------------------------------------------------
// Kernel 2: one LSTM timestep. gates = xg_t + h_prev @ W_hh^T, cell update,
// and fused partial output projection (warp-reduced atomicAdd into out).
// Grid: (H/64 = 8 j-tiles) x (B/16 = 16 b-tiles) = 128 blocks, 256 threads.
// Thread owns (4 batches) x (4 gates of ONE hidden column j).
// ---------------------------------------------------------------------------
__global__ void step_kernel(const float* __restrict__ h0,
                            const float* __restrict__ c0,
                            const float* __restrict__ W_hh,
                            const float* __restrict__ W_out,
                            float* __restrict__ out,
                            int t) {
    __shared__ float wS[32][257]; // [kk][c], c = gate*64 + jg ; pad 257 => conflict-free
    __shared__ float hS[32][17];  // [kk][b]
    const int tid = threadIdx.x;
    const int j0  = blockIdx.x * 64;
    const int b0  = blockIdx.y * 16;
    const int jg  = tid & 63;    // hidden column within tile
    const int bg  = tid >> 6;    // batch group (x4)

    const float* hprev = (t == 0) ? h0 : g_h[(t - 1) & 1];
    const float* cin   = (t == 0) ? c0 : g_c;
    float*       hcur  = g_h[t & 1];

    float acc[4][4] = {}; // [bb][gate]

    for (int k0 = 0; k0 < H_SZ; k0 += 32) {
        // W tile: 256 rows (4 gates x 64 j) x 32 k, coalesced float4 reads
        #pragma unroll
        for (int i = 0; i < 8; i++) {
            int idx = tid + i * 256;        // float4 index, 0..2047
            int cc  = idx >> 3;             // 0..255
            int kq  = idx & 7;              // 0..7
            int row = (cc >> 6) * H_SZ + j0 + (cc & 63);
            const float4 w4 = *reinterpret_cast<const float4*>(
                &W_hh[(size_t)row * H_SZ + k0 + kq * 4]);
            wS[kq * 4 + 0][cc] = w4.x;
            wS[kq * 4 + 1][cc] = w4.y;
            wS[kq * 4 + 2][cc] = w4.z;
            wS[kq * 4 + 3][cc] = w4.w;
        }
        // h tile: 16 b x 32 k
        if (tid < 128) {
            int b  = tid >> 3;
            int kq = tid & 7;
            const float4 h4 = *reinterpret_cast<const float4*>(
                &hprev[(size_t)(b0 + b) * H_SZ + k0 + kq * 4]);
            hS[kq * 4 + 0][b] = h4.x;
            hS[kq * 4 + 1][b] = h4.y;
            hS[kq * 4 + 2][b] = h4.z;
            hS[kq * 4 + 3][b] = h4.w;
        }
        __syncthreads();
        #pragma unroll
        for (int kk = 0; kk < 32; kk++) {
            float w[4], h[4];
            #pragma unroll
            for (int g = 0; g < 4; g++) w[g] = wS[kk][g * 64 + jg];
            #pragma unroll
            for (int bb = 0; bb < 4; bb++) h[bb] = hS[kk][bg * 4 + bb];
            #pragma unroll
            for (int bb = 0; bb < 4; bb++)
                #pragma unroll
                for (int g = 0; g < 4; g++)
                    acc[bb][g] = fmaf(h[bb], w[g], acc[bb][g]);
        }
        __syncthreads();
    }

    // Epilogue: add xg, activations, cell update, write h, fused out projection.
    const float* xg_t = g_xg + (size_t)t * B_SZ * G4;
    const int j = j0 + jg;
    const float wout = W_out[j];
    #pragma unroll
    for (int bb = 0; bb < 4; bb++) {
        int b = b0 + bg * 4 + bb;
        size_t xo = (size_t)b * G4;
        float gi = acc[bb][0] + xg_t[xo + 0 * H_SZ + j];
        float gf = acc[bb][1] + xg_t[xo + 1 * H_SZ + j];
        float gg = acc[bb][2] + xg_t[xo + 2 * H_SZ + j];
        float go = acc[bb][3] + xg_t[xo + 3 * H_SZ + j];
        gi = 1.0f / (1.0f + __expf(-gi));
        gf = 1.0f / (1.0f + __expf(-gf));
        gg = tanhf(gg);
        go = 1.0f / (1.0f + __expf(-go));
        int ci = b * H_SZ + j;
        float cn = gf * cin[ci] + gi * gg;
        g_c[ci]  = cn;
        float hv = go * tanhf(cn);
        hcur[ci] = hv;
        // fused output projection: warp-reduce hv*W_out[j] over 32 j's
        float s = hv * wout;
        #pragma unroll
        for (int off = 16; off; off >>= 1) s += __shfl_xor_sync(0xffffffffu, s, off);
        if ((tid & 31) == 0) atomicAdd(&out[(size_t)b * T_STEPS + t], s);
    }
}

// ---------------------------------------------------------------------------
extern "C" void kernel_launch(void* const* d_in, const int* in_sizes, int n_in,
                              void* d_out, int out_size) {
    const float* obs   = (const float*)d_in[0];
    const float* act   = (const float*)d_in[1];
    const float* h0    = (const float*)d_in[2];
    const float* c0    = (const float*)d_in[3];
    const float* W_ih  = (const float*)d_in[4];
    const float* W_hh  = (const float*)d_in[5];
    const float* b_ih  = (const float*)d_in[6];
    const float* b_hh  = (const float*)d_in[7];
    const float* W_out = (const float*)d_in[8];
    const float* b_out = (const float*)d_in[9];
    float* out = (float*)d_out;

    // 0) seed out with bias (accumulated into by step kernels)
    init_out_kernel<<<(B_SZ * T_STEPS + 255) / 256, 256>>>(out, b_out);

    // 1) Input projection for all timesteps
    dim3 gx(G4 / 64, (B_SZ * T_STEPS) / 64);
    xg_kernel<<<gx, 256>>>(obs, act, W_ih, b_ih, b_hh);

    // 2) Sequential recurrence: one kernel per timestep (graph nodes)
    dim3 gs(H_SZ / 64, B_SZ / 16);
    for (int t = 0; t < T_STEPS; t++)
        step_kernel<<<gs, 256>>>(h0, c0, W_hh, W_out, out, t);
}

// round 4
// speedup vs baseline: 1.0002x; 1.0002x over previous
#include <cuda_runtime.h>
#include <cstddef>

#define T_STEPS 512
#define B_SZ    256
#define H_SZ    512
#define I_SZ    192
#define G4      2048   // 4*H

// Scratch (allocation-free rule: __device__ globals)
__device__ float g_xg[(size_t)T_STEPS * B_SZ * G4];   // [T][B][4H]  (1 GiB)
__device__ float g_h [2][(size_t)B_SZ * H_SZ];        // double-buffered hidden (4 MiB)
__device__ float g_c [(size_t)B_SZ * H_SZ];           // cell state (in-place per step)

// ---------------------------------------------------------------------------
// Kernel 0: seed output with bias (d_out is poisoned before timing)
// ---------------------------------------------------------------------------
__global__ void init_out_kernel(float* __restrict__ out, const float* __restrict__ b_out) {
    int i = blockIdx.x * blockDim.x + threadIdx.x;
    if (i < B_SZ * T_STEPS) out[i] = b_out[0];
}

// ---------------------------------------------------------------------------
// Kernel 1: xg[t][b][g] = concat(obs,act)[b,t,:] . W_ih[g,:] + b_ih[g] + b_hh[g]
// Tiled fp32 GEMM: M = B*T (131072), N = 4H (2048), K = I (192).
// Block tile 64x64, 256 threads, 4x4 register microtile.
// ---------------------------------------------------------------------------
__global__ void xg_kernel(const float* __restrict__ obs, const float* __restrict__ act,
                          const float* __restrict__ W_ih, const float* __restrict__ b_ih,
                          const float* __restrict__ b_hh) {
    __shared__ float aS[16][65]; // [kk][m] k-major, padded
    __shared__ float bS[16][65]; // [kk][n]
    const int m0  = blockIdx.y * 64;
    const int n0  = blockIdx.x * 64;
    const int tid = threadIdx.x;
    const int nIdx = tid & 15;   // n-lane (x4 strided)
    const int mIdx = tid >> 4;   // m-group (x4 contiguous)
    float acc[4][4] = {};

    for (int k0 = 0; k0 < I_SZ; k0 += 16) {
        #pragma unroll
        for (int i = 0; i < 4; i++) {
            int idx = tid + i * 256;
            int r = idx >> 4, kk = idx & 15;
            int m = m0 + r;
            int b = m >> 9, t = m & 511;
            int k = k0 + kk;
            float v;
            if (k < 128) v = obs[((size_t)(b * T_STEPS + t)) * 128 + k];
            else         v = act[((size_t)(b * T_STEPS + t)) * 64 + (k - 128)];
            aS[kk][r] = v;
        }
        #pragma unroll
        for (int i = 0; i < 4; i++) {
            int idx = tid + i * 256;
            int r = idx >> 4, kk = idx & 15;
            bS[kk][r] = W_ih[(size_t)(n0 + r) * I_SZ + (k0 + kk)];
        }
        __syncthreads();
        #pragma unroll
        for (int kk = 0; kk < 16; kk++) {
            float a[4], bv[4];
            #pragma unroll
            for (int ii = 0; ii < 4; ii++) a[ii] = aS[kk][mIdx * 4 + ii];
            #pragma unroll
            for (int jj = 0; jj < 4; jj++) bv[jj] = bS[kk][nIdx + 16 * jj];
            #pragma unroll
            for (int ii = 0; ii < 4; ii++)
                #pragma unroll
                for (int jj = 0; jj < 4; jj++)
                    acc[ii][jj] = fmaf(a[ii], bv[jj], acc[ii][jj]);
        }
        __syncthreads();
    }
    #pragma unroll
    for (int jj = 0; jj < 4; jj++) {
        int n = n0 + nIdx + 16 * jj;
        float bias = b_ih[n] + b_hh[n];
        #pragma unroll
        for (int ii = 0; ii < 4; ii++) {
            int m = m0 + mIdx * 4 + ii;
            int b = m >> 9, t = m & 511;
            g_xg[((size_t)t * B_SZ + b) * G4 + n] = acc[ii][jj] + bias;
        }
    }
}

// ---------------------------------------------------------------------------
// Kernel 2: one LSTM timestep. gates = xg_t + h_prev @ W_hh^T, cell update,
// and fused partial output projection (warp-reduced atomicAdd into out).
// Grid: (H/64 = 8 j-tiles) x (B/16 = 16 b-tiles) = 128 blocks, 256 threads.
// Thread owns (4 batches) x (4 gates of ONE hidden column j).
// ---------------------------------------------------------------------------
__global__ void step_kernel(const float* __restrict__ h0,
                            const float* __restrict__ c0,
                            const float* __restrict__ W_hh,
                            const float* __restrict__ W_out,
                            float* __restrict__ out,
                            int t) {
    __shared__ float wS[32][257]; // [kk][c], c = gate*64 + jg ; pad 257 => conflict-free
    __shared__ float hS[32][17];  // [kk][b]
    const int tid = threadIdx.x;
    const int j0  = blockIdx.x * 64;
    const int b0  = blockIdx.y * 16;
    const int jg  = tid & 63;    // hidden column within tile
    const int bg  = tid >> 6;    // batch group (x4)

    const float* hprev = (t == 0) ? h0 : g_h[(t - 1) & 1];
    const float* cin   = (t == 0) ? c0 : g_c;
    float*       hcur  = g_h[t & 1];

    float acc[4][4] = {}; // [bb][gate]

    for (int k0 = 0; k0 < H_SZ; k0 += 32) {
        // W tile: 256 rows (4 gates x 64 j) x 32 k, coalesced float4 reads
        #pragma unroll
        for (int i = 0; i < 8; i++) {
            int idx = tid + i * 256;        // float4 index, 0..2047
            int cc  = idx >> 3;             // 0..255
            int kq  = idx & 7;              // 0..7
            int row = (cc >> 6) * H_SZ + j0 + (cc & 63);
            const float4 w4 = *reinterpret_cast<const float4*>(
                &W_hh[(size_t)row * H_SZ + k0 + kq * 4]);
            wS[kq * 4 + 0][cc] = w4.x;
            wS[kq * 4 + 1][cc] = w4.y;
            wS[kq * 4 + 2][cc] = w4.z;
            wS[kq * 4 + 3][cc] = w4.w;
        }
        // h tile: 16 b x 32 k
        if (tid < 128) {
            int b  = tid >> 3;
            int kq = tid & 7;
            const float4 h4 = *reinterpret_cast<const float4*>(
                &hprev[(size_t)(b0 + b) * H_SZ + k0 + kq * 4]);
            hS[kq * 4 + 0][b] = h4.x;
            hS[kq * 4 + 1][b] = h4.y;
            hS[kq * 4 + 2][b] = h4.z;
            hS[kq * 4 + 3][b] = h4.w;
        }
        __syncthreads();
        #pragma unroll
        for (int kk = 0; kk < 32; kk++) {
            float w[4], h[4];
            #pragma unroll
            for (int g = 0; g < 4; g++) w[g] = wS[kk][g * 64 + jg];
            #pragma unroll
            for (int bb = 0; bb < 4; bb++) h[bb] = hS[kk][bg * 4 + bb];
            #pragma unroll
            for (int bb = 0; bb < 4; bb++)
                #pragma unroll
                for (int g = 0; g < 4; g++)
                    acc[bb][g] = fmaf(h[bb], w[g], acc[bb][g]);
        }
        __syncthreads();
    }

    // Epilogue: add xg, activations, cell update, write h, fused out projection.
    const float* xg_t = g_xg + (size_t)t * B_SZ * G4;
    const int j = j0 + jg;
    const float wout = W_out[j];
    #pragma unroll
    for (int bb = 0; bb < 4; bb++) {
        int b = b0 + bg * 4 + bb;
        size_t xo = (size_t)b * G4;
        float gi = acc[bb][0] + xg_t[xo + 0 * H_SZ + j];
        float gf = acc[bb][1] + xg_t[xo + 1 * H_SZ + j];
        float gg = acc[bb][2] + xg_t[xo + 2 * H_SZ + j];
        float go = acc[bb][3] + xg_t[xo + 3 * H_SZ + j];
        gi = 1.0f / (1.0f + __expf(-gi));
        gf = 1.0f / (1.0f + __expf(-gf));
        gg = tanhf(gg);
        go = 1.0f / (1.0f + __expf(-go));
        int ci = b * H_SZ + j;
        float cn = gf * cin[ci] + gi * gg;
        g_c[ci]  = cn;
        float hv = go * tanhf(cn);
        hcur[ci] = hv;
        // fused output projection: warp-reduce hv*W_out[j] over 32 j's
        float s = hv * wout;
        #pragma unroll
        for (int off = 16; off; off >>= 1) s += __shfl_xor_sync(0xffffffffu, s, off);
        if ((tid & 31) == 0) atomicAdd(&out[(size_t)b * T_STEPS + t], s);
    }
}

// ---------------------------------------------------------------------------
extern "C" void kernel_launch(void* const* d_in, const int* in_sizes, int n_in,
                              void* d_out, int out_size) {
    const float* obs   = (const float*)d_in[0];
    const float* act   = (const float*)d_in[1];
    const float* h0    = (const float*)d_in[2];
    const float* c0    = (const float*)d_in[3];
    const float* W_ih  = (const float*)d_in[4];
    const float* W_hh  = (const float*)d_in[5];
    const float* b_ih  = (const float*)d_in[6];
    const float* b_hh  = (const float*)d_in[7];
    const float* W_out = (const float*)d_in[8];
    const float* b_out = (const float*)d_in[9];
    float* out = (float*)d_out;

    // 0) seed out with bias (accumulated into by step kernels)
    init_out_kernel<<<(B_SZ * T_STEPS + 255) / 256, 256>>>(out, b_out);

    // 1) Input projection for all timesteps
    dim3 gx(G4 / 64, (B_SZ * T_STEPS) / 64);
    xg_kernel<<<gx, 256>>>(obs, act, W_ih, b_ih, b_hh);

    // 2) Sequential recurrence: one kernel per timestep (graph nodes)
    dim3 gs(H_SZ / 64, B_SZ / 16);
    for (int t = 0; t < T_STEPS; t++)
        step_kernel<<<gs, 256>>>(h0, c0, W_hh, W_out, out, t);
}

// round 6
// speedup vs baseline: 1.9270x; 1.9265x over previous
#include <cuda_runtime.h>
#include <cuda_bf16.h>
#include <cstdint>
#include <cstddef>

#define T_STEPS 512
#define B_SZ    256
#define H_SZ    512
#define I_SZ    192
#define G4      2048   // 4*H

// ---------------------------------------------------------------------------
// Scratch (allocation-free rule: __device__ globals)
// ---------------------------------------------------------------------------
__device__ float         g_xg[(size_t)T_STEPS * B_SZ * G4];  // [T][B][4H] fp32
__device__ __nv_bfloat16 g_hhi[2][B_SZ * H_SZ];              // h hi, double-buffered
__device__ __nv_bfloat16 g_hlo[2][B_SZ * H_SZ];              // h lo
__device__ float         g_c  [B_SZ * H_SZ];                 // cell state fp32
__device__ __nv_bfloat16 g_whi[(size_t)G4 * H_SZ];           // W_hh hi
__device__ __nv_bfloat16 g_wlo[(size_t)G4 * H_SZ];           // W_hh lo

// ---------------------------------------------------------------------------
// Warp MMA helpers (sm_80+ baseline instructions, no 'a'-features)
// ---------------------------------------------------------------------------
__device__ __forceinline__ uint32_t smem_u32(const void* p) {
    uint32_t a;
    asm("{ .reg .u64 t; cvta.to.shared.u64 t, %1; cvt.u32.u64 %0, t; }" : "=r"(a) : "l"(p));
    return a;
}
__device__ __forceinline__ void ldsm_x4(uint32_t r[4], uint32_t addr) {
    asm volatile("ldmatrix.sync.aligned.m8n8.x4.shared.b16 {%0,%1,%2,%3}, [%4];"
                 : "=r"(r[0]), "=r"(r[1]), "=r"(r[2]), "=r"(r[3]) : "r"(addr));
}
__device__ __forceinline__ void ldsm_x2(uint32_t r[2], uint32_t addr) {
    asm volatile("ldmatrix.sync.aligned.m8n8.x2.shared.b16 {%0,%1}, [%2];"
                 : "=r"(r[0]), "=r"(r[1]) : "r"(addr));
}
__device__ __forceinline__ void mma16816(float c[4], const uint32_t a[4], const uint32_t b[2]) {
    asm volatile("mma.sync.aligned.m16n8k16.row.col.f32.bf16.bf16.f32 "
                 "{%0,%1,%2,%3}, {%4,%5,%6,%7}, {%8,%9}, {%0,%1,%2,%3};"
                 : "+f"(c[0]), "+f"(c[1]), "+f"(c[2]), "+f"(c[3])
                 : "r"(a[0]), "r"(a[1]), "r"(a[2]), "r"(a[3]), "r"(b[0]), "r"(b[1]));
}

// ---------------------------------------------------------------------------
// Kernel 0: seed output with bias (d_out is poisoned before timing)
// ---------------------------------------------------------------------------
__global__ void init_out_kernel(float* __restrict__ out, const float* __restrict__ b_out) {
    int i = blockIdx.x * blockDim.x + threadIdx.x;
    if (i < B_SZ * T_STEPS) out[i] = b_out[0];
}

// ---------------------------------------------------------------------------
// Split kernels: fp32 -> bf16 hi + bf16 lo
// ---------------------------------------------------------------------------
__global__ void split_w_kernel(const float* __restrict__ W) {
    int i = blockIdx.x * blockDim.x + threadIdx.x;
    if (i < G4 * H_SZ) {
        float w = W[i];
        __nv_bfloat16 hi = __float2bfloat16(w);
        g_whi[i] = hi;
        g_wlo[i] = __float2bfloat16(w - __bfloat162float(hi));
    }
}
__global__ void split_h0_kernel(const float* __restrict__ h0) {
    int i = blockIdx.x * blockDim.x + threadIdx.x;
    if (i < B_SZ * H_SZ) {
        float h = h0[i];
        __nv_bfloat16 hi = __float2bfloat16(h);
        g_hhi[1][i] = hi;   // t=0 reads buffer (0+1)&1 = 1
        g_hlo[1][i] = __float2bfloat16(h - __bfloat162float(hi));
    }
}

// ---------------------------------------------------------------------------
// Kernel 1: xg = concat(obs,act) @ W_ih^T + b_ih + b_hh  (fp32, unchanged)
// ---------------------------------------------------------------------------
__global__ void xg_kernel(const float* __restrict__ obs, const float* __restrict__ act,
                          const float* __restrict__ W_ih, const float* __restrict__ b_ih,
                          const float* __restrict__ b_hh) {
    __shared__ float aS[16][65];
    __shared__ float bS[16][65];
    const int m0  = blockIdx.y * 64;
    const int n0  = blockIdx.x * 64;
    const int tid = threadIdx.x;
    const int nIdx = tid & 15;
    const int mIdx = tid >> 4;
    float acc[4][4] = {};

    for (int k0 = 0; k0 < I_SZ; k0 += 16) {
        #pragma unroll
        for (int i = 0; i < 4; i++) {
            int idx = tid + i * 256;
            int r = idx >> 4, kk = idx & 15;
            int m = m0 + r;
            int b = m >> 9, t = m & 511;
            int k = k0 + kk;
            float v;
            if (k < 128) v = obs[((size_t)(b * T_STEPS + t)) * 128 + k];
            else         v = act[((size_t)(b * T_STEPS + t)) * 64 + (k - 128)];
            aS[kk][r] = v;
        }
        #pragma unroll
        for (int i = 0; i < 4; i++) {
            int idx = tid + i * 256;
            int r = idx >> 4, kk = idx & 15;
            bS[kk][r] = W_ih[(size_t)(n0 + r) * I_SZ + (k0 + kk)];
        }
        __syncthreads();
        #pragma unroll
        for (int kk = 0; kk < 16; kk++) {
            float a[4], bv[4];
            #pragma unroll
            for (int ii = 0; ii < 4; ii++) a[ii] = aS[kk][mIdx * 4 + ii];
            #pragma unroll
            for (int jj = 0; jj < 4; jj++) bv[jj] = bS[kk][nIdx + 16 * jj];
            #pragma unroll
            for (int ii = 0; ii < 4; ii++)
                #pragma unroll
                for (int jj = 0; jj < 4; jj++)
                    acc[ii][jj] = fmaf(a[ii], bv[jj], acc[ii][jj]);
        }
        __syncthreads();
    }
    #pragma unroll
    for (int jj = 0; jj < 4; jj++) {
        int n = n0 + nIdx + 16 * jj;
        float bias = b_ih[n] + b_hh[n];
        #pragma unroll
        for (int ii = 0; ii < 4; ii++) {
            int m = m0 + mIdx * 4 + ii;
            int b = m >> 9, t = m & 511;
            g_xg[((size_t)t * B_SZ + b) * G4 + n] = acc[ii][jj] + bias;
        }
    }
}

// ---------------------------------------------------------------------------
// Kernel 2: one LSTM timestep via warp-level bf16 HMMA (mma.sync m16n8k16).
// Grid (32, 4): x = j-tile (16 j), y = batch-tile (64 b). 256 thr = 8 warps.
// Block tile: M=64 batch x N=64 (gate*16 + jj). 3-term split-bf16 fp32 GEMM.
// K = 512 in 8 chunks of 64. Smem rows padded to 48B (ldmatrix conflict-free).
// ---------------------------------------------------------------------------
struct __align__(16) StepSmem {
    union {
        struct {
            __nv_bfloat16 Ahi[4][64][24];  // [k16-group][m][16 valid + 8 pad]
            __nv_bfloat16 Alo[4][64][24];
            __nv_bfloat16 Bhi[4][64][24];  // [k16-group][n][...]
            __nv_bfloat16 Blo[4][64][24];
        };
        float Cx[64][65];                  // epilogue exchange (aliases tiles)
    };
};

__global__ void __launch_bounds__(256, 1)
step_mma_kernel(const float* __restrict__ c0,
                const float* __restrict__ W_out,
                float* __restrict__ out,
                int t) {
    __shared__ StepSmem sm;
    const int tid  = threadIdx.x;
    const int wid  = tid >> 5;
    const int lane = tid & 31;
    const int j0     = blockIdx.x * 16;  // hidden-column tile
    const int m_base = blockIdx.y * 64;  // batch tile

    const int pb = (t + 1) & 1;
    const int cb = t & 1;
    const __nv_bfloat16* hhi = g_hhi[pb];
    const __nv_bfloat16* hlo = g_hlo[pb];

    const int mw = wid >> 1;   // warp m-tile: rows mw*16 .. +15
    const int nw = wid & 1;    // warp n-tile: cols nw*32 .. +31
    const int m0 = mw * 16;

    // Per-lane ldmatrix base offsets (element index into [64][24] bf16 plane)
    const int a_row  = m0 + (lane & 7) + 8 * ((lane >> 3) & 1);
    const int a_kh   = 8 * (lane >> 4);
    const int a_off  = a_row * 24 + a_kh;
    const int b_lane = lane & 15;
    const int b_row0 = nw * 32 + (b_lane & 7);       // + g4*8 per n-group
    const int b_kh   = 8 * ((b_lane >> 3) & 1);

    const uint32_t sAhi = smem_u32(&sm.Ahi[0][0][0]);
    const uint32_t sAlo = smem_u32(&sm.Alo[0][0][0]);
    const uint32_t sBhi = smem_u32(&sm.Bhi[0][0][0]);
    const uint32_t sBlo = smem_u32(&sm.Blo[0][0][0]);

    float c[4][4] = {};   // 4 n-fragments x 4 accum regs (warp tile 16x32)

    for (int kc = 0; kc < 8; kc++) {
        // ---- load chunk: A (h) 64x64 hi/lo, B (W rows) 64x64 hi/lo ----
        #pragma unroll
        for (int i = 0; i < 2; i++) {
            int flat = tid + i * 256;        // 0..511
            int row = flat >> 3, q = flat & 7;
            // A: h[m_base+row][kc*64 + q*8 .. +7]
            size_t ga = (size_t)(m_base + row) * H_SZ + kc * 64 + q * 8;
            uint4 va_hi = *reinterpret_cast<const uint4*>(hhi + ga);
            uint4 va_lo = *reinterpret_cast<const uint4*>(hlo + ga);
            *reinterpret_cast<uint4*>(&sm.Ahi[q >> 1][row][(q & 1) * 8]) = va_hi;
            *reinterpret_cast<uint4*>(&sm.Alo[q >> 1][row][(q & 1) * 8]) = va_lo;
            // B: W_hh row (gate*512 + j0 + jj), n = gate*16 + jj
            int gate = row >> 4, jj = row & 15;
            size_t gb = (size_t)(gate * H_SZ + j0 + jj) * H_SZ + kc * 64 + q * 8;
            uint4 vb_hi = *reinterpret_cast<const uint4*>(g_whi + gb);
            uint4 vb_lo = *reinterpret_cast<const uint4*>(g_wlo + gb);
            *reinterpret_cast<uint4*>(&sm.Bhi[q >> 1][row][(q & 1) * 8]) = vb_hi;
            *reinterpret_cast<uint4*>(&sm.Blo[q >> 1][row][(q & 1) * 8]) = vb_lo;
        }
        __syncthreads();

        // ---- MMA phase: 4 k-steps of 16 ----
        #pragma unroll
        for (int ks = 0; ks < 4; ks++) {
            const uint32_t plane = (uint32_t)ks * (64 * 24 * 2);  // bytes per k16-group
            uint32_t ahi[4], alo[4];
            ldsm_x4(ahi, sAhi + plane + a_off * 2);
            ldsm_x4(alo, sAlo + plane + a_off * 2);
            #pragma unroll
            for (int g4 = 0; g4 < 4; g4++) {
                uint32_t bhi[2], blo[2];
                uint32_t boff = plane + ((b_row0 + g4 * 8) * 24 + b_kh) * 2;
                ldsm_x2(bhi, sBhi + boff);
                ldsm_x2(blo, sBlo + boff);
                mma16816(c[g4], ahi, bhi);
                mma16816(c[g4], ahi, blo);
                mma16816(c[g4], alo, bhi);
            }
        }
        __syncthreads();
    }

    // ---- write warp fragments to exchange buffer ----
    {
        const int g  = lane >> 2;
        const int tq = lane & 3;
        #pragma unroll
        for (int g4 = 0; g4 < 4; g4++) {
            int n = nw * 32 + g4 * 8 + 2 * tq;
            sm.Cx[m0 + g][n]         = c[g4][0];
            sm.Cx[m0 + g][n + 1]     = c[g4][1];
            sm.Cx[m0 + g + 8][n]     = c[g4][2];
            sm.Cx[m0 + g + 8][n + 1] = c[g4][3];
        }
    }
    __syncthreads();

    // ---- epilogue: thread owns (m = tid>>2, 4 j's = (tid&3)*4 ..+3) ----
    const int m  = tid >> 2;
    const int jg = tid & 3;
    const int b  = m_base + m;
    const float* xg_t = g_xg + (size_t)t * B_SZ * G4 + (size_t)b * G4;
    const float* cin  = (t == 0) ? (c0 + (size_t)b * H_SZ) : (g_c + (size_t)b * H_SZ);
    float s = 0.f;
    uint32_t hi_pack[2], lo_pack[2];
    #pragma unroll
    for (int u = 0; u < 4; u++) {
        const int jj = jg * 4 + u;
        const int j  = j0 + jj;
        float gi = sm.Cx[m][0 * 16 + jj] + xg_t[0 * H_SZ + j];
        float gf = sm.Cx[m][1 * 16 + jj] + xg_t[1 * H_SZ + j];
        float gg = sm.Cx[m][2 * 16 + jj] + xg_t[2 * H_SZ + j];
        float go = sm.Cx[m][3 * 16 + jj] + xg_t[3 * H_SZ + j];
        gi = 1.0f / (1.0f + __expf(-gi));
        gf = 1.0f / (1.0f + __expf(-gf));
        gg = tanhf(gg);
        go = 1.0f / (1.0f + __expf(-go));
        float cn = gf * cin[j] + gi * gg;
        g_c[(size_t)b * H_SZ + j] = cn;
        float hv = go * tanhf(cn);
        s += hv * W_out[j];
        __nv_bfloat16 hvi = __float2bfloat16(hv);
        __nv_bfloat16 hvl = __float2bfloat16(hv - __bfloat162float(hvi));
        uint32_t uhi = (uint32_t)__bfloat16_as_ushort(hvi);
        uint32_t ulo = (uint32_t)__bfloat16_as_ushort(hvl);
        if (u & 1) { hi_pack[u >> 1] |= uhi << 16; lo_pack[u >> 1] |= ulo << 16; }
        else       { hi_pack[u >> 1]  = uhi;       lo_pack[u >> 1]  = ulo; }
    }
    size_t ho = (size_t)b * H_SZ + j0 + jg * 4;
    *reinterpret_cast<uint2*>(&g_hhi[cb][ho]) = make_uint2(hi_pack[0], hi_pack[1]);
    *reinterpret_cast<uint2*>(&g_hlo[cb][ho]) = make_uint2(lo_pack[0], lo_pack[1]);

    // reduce fused out-projection across the 4 threads sharing this m
    s += __shfl_xor_sync(0xffffffffu, s, 1);
    s += __shfl_xor_sync(0xffffffffu, s, 2);
    if (jg == 0) atomicAdd(&out[(size_t)b * T_STEPS + t], s);
}

// ---------------------------------------------------------------------------
extern "C" void kernel_launch(void* const* d_in, const int* in_sizes, int n_in,
                              void* d_out, int out_size) {
    const float* obs   = (const float*)d_in[0];
    const float* act   = (const float*)d_in[1];
    const float* h0    = (const float*)d_in[2];
    const float* c0    = (const float*)d_in[3];
    const float* W_ih  = (const float*)d_in[4];
    const float* W_hh  = (const float*)d_in[5];
    const float* b_ih  = (const float*)d_in[6];
    const float* b_hh  = (const float*)d_in[7];
    const float* W_out = (const float*)d_in[8];
    const float* b_out = (const float*)d_in[9];
    float* out = (float*)d_out;

    init_out_kernel<<<(B_SZ * T_STEPS + 255) / 256, 256>>>(out, b_out);
    split_w_kernel<<<(G4 * H_SZ + 255) / 256, 256>>>(W_hh);
    split_h0_kernel<<<(B_SZ * H_SZ + 255) / 256, 256>>>(h0);

    dim3 gx(G4 / 64, (B_SZ * T_STEPS) / 64);
    xg_kernel<<<gx, 256>>>(obs, act, W_ih, b_ih, b_hh);

    dim3 gs(32, 4);
    for (int t = 0; t < T_STEPS; t++)
        step_mma_kernel<<<gs, 256>>>(c0, W_out, out, t);
}

// round 8
// speedup vs baseline: 2.1804x; 1.1315x over previous
#include <cuda_runtime.h>
#include <cuda_bf16.h>
#include <cstdint>
#include <cstddef>

#define T_STEPS 512
#define B_SZ    256
#define H_SZ    512
#define I_SZ    192
#define G4      2048   // 4*H
#define MT      131072 // B*T

// ---------------------------------------------------------------------------
// Scratch (allocation-free rule: __device__ globals)
// ---------------------------------------------------------------------------
__device__ float         g_xg[(size_t)T_STEPS * B_SZ * G4];  // [T][B][4H] fp32
__device__ __nv_bfloat16 g_hhi[2][B_SZ * H_SZ];
__device__ __nv_bfloat16 g_hlo[2][B_SZ * H_SZ];
__device__ float         g_c  [B_SZ * H_SZ];
__device__ __nv_bfloat16 g_whi[(size_t)G4 * H_SZ];           // W_hh split
__device__ __nv_bfloat16 g_wlo[(size_t)G4 * H_SZ];
__device__ __nv_bfloat16 g_xhi[(size_t)MT * I_SZ];           // concat(obs,act) split
__device__ __nv_bfloat16 g_xlo[(size_t)MT * I_SZ];
__device__ __nv_bfloat16 g_wihi[(size_t)G4 * I_SZ];          // W_ih split
__device__ __nv_bfloat16 g_wilo[(size_t)G4 * I_SZ];

// ---------------------------------------------------------------------------
// Helpers (sm_80+ baseline instructions only — no 'a'-features)
// ---------------------------------------------------------------------------
__device__ __forceinline__ uint32_t smem_u32(const void* p) {
    uint32_t a;
    asm("{ .reg .u64 t; cvta.to.shared.u64 t, %1; cvt.u32.u64 %0, t; }" : "=r"(a) : "l"(p));
    return a;
}
__device__ __forceinline__ void ldsm_x4(uint32_t r[4], uint32_t addr) {
    asm volatile("ldmatrix.sync.aligned.m8n8.x4.shared.b16 {%0,%1,%2,%3}, [%4];"
                 : "=r"(r[0]), "=r"(r[1]), "=r"(r[2]), "=r"(r[3]) : "r"(addr));
}
__device__ __forceinline__ void ldsm_x2(uint32_t r[2], uint32_t addr) {
    asm volatile("ldmatrix.sync.aligned.m8n8.x2.shared.b16 {%0,%1}, [%2];"
                 : "=r"(r[0]), "=r"(r[1]) : "r"(addr));
}
__device__ __forceinline__ void mma16816(float c[4], const uint32_t a[4], const uint32_t b[2]) {
    asm volatile("mma.sync.aligned.m16n8k16.row.col.f32.bf16.bf16.f32 "
                 "{%0,%1,%2,%3}, {%4,%5,%6,%7}, {%8,%9}, {%0,%1,%2,%3};"
                 : "+f"(c[0]), "+f"(c[1]), "+f"(c[2]), "+f"(c[3])
                 : "r"(a[0]), "r"(a[1]), "r"(a[2]), "r"(a[3]), "r"(b[0]), "r"(b[1]));
}
#define CP_ASYNC16(saddr, gptr) \
    asm volatile("cp.async.cg.shared.global [%0], [%1], 16;" \
                 :: "r"(saddr), "l"((const void*)(gptr)))
#define CP_COMMIT() asm volatile("cp.async.commit_group;" ::: "memory")

// ---------------------------------------------------------------------------
// Kernel 0: seed output with bias
// ---------------------------------------------------------------------------
__global__ void init_out_kernel(float* __restrict__ out, const float* __restrict__ b_out) {
    int i = blockIdx.x * blockDim.x + threadIdx.x;
    if (i < B_SZ * T_STEPS) out[i] = b_out[0];
}

// ---------------------------------------------------------------------------
// Split kernels: fp32 -> bf16 hi + bf16 lo
// ---------------------------------------------------------------------------
__global__ void split_w_kernel(const float* __restrict__ W) {
    int i = blockIdx.x * blockDim.x + threadIdx.x;
    if (i < G4 * H_SZ) {
        float w = W[i];
        __nv_bfloat16 hi = __float2bfloat16(w);
        g_whi[i] = hi;
        g_wlo[i] = __float2bfloat16(w - __bfloat162float(hi));
    }
}
__global__ void split_wih_kernel(const float* __restrict__ W) {
    int i = blockIdx.x * blockDim.x + threadIdx.x;
    if (i < G4 * I_SZ) {
        float w = W[i];
        __nv_bfloat16 hi = __float2bfloat16(w);
        g_wihi[i] = hi;
        g_wilo[i] = __float2bfloat16(w - __bfloat162float(hi));
    }
}
__global__ void split_h0_kernel(const float* __restrict__ h0) {
    int i = blockIdx.x * blockDim.x + threadIdx.x;
    if (i < B_SZ * H_SZ) {
        float h = h0[i];
        __nv_bfloat16 hi = __float2bfloat16(h);
        g_hhi[1][i] = hi;   // t=0 reads buffer (0+1)&1 = 1
        g_hlo[1][i] = __float2bfloat16(h - __bfloat162float(hi));
    }
}
__global__ void split_x_kernel(const float* __restrict__ obs, const float* __restrict__ act) {
    size_t i = (size_t)blockIdx.x * blockDim.x + threadIdx.x;
    if (i >= (size_t)MT * I_SZ) return;
    int m = (int)(i / I_SZ), k = (int)(i % I_SZ);
    int b = m >> 9, t = m & 511;
    float v = (k < 128) ? obs[((size_t)(b * T_STEPS + t)) * 128 + k]
                        : act[((size_t)(b * T_STEPS + t)) * 64 + (k - 128)];
    __nv_bfloat16 hi = __float2bfloat16(v);
    g_xhi[i] = hi;
    g_xlo[i] = __float2bfloat16(v - __bfloat162float(hi));
}

// ---------------------------------------------------------------------------
// Shared tile struct for the single-stage xg kernel (48 KB, unioned with Cx)
// Row pitch 24 bf16 (48B) => ldmatrix conflict-free (verified R6).
// ---------------------------------------------------------------------------
struct __align__(16) TileSmem {
    union {
        struct {
            __nv_bfloat16 Ahi[4][64][24];
            __nv_bfloat16 Alo[4][64][24];
            __nv_bfloat16 Bhi[4][64][24];
            __nv_bfloat16 Blo[4][64][24];
        };
        float Cx[64][65];
    };
};

// ---------------------------------------------------------------------------
// Kernel 1: xg = concat(obs,act) @ W_ih^T + (b_ih + b_hh), via split-bf16 HMMA.
// Grid (32 n-tiles, 2048 m-tiles), 256 thr. Tile M=64 x N=64, K=192 (3 chunks).
// ---------------------------------------------------------------------------
__global__ void __launch_bounds__(256)
xg_mma_kernel(const float* __restrict__ b_ih, const float* __restrict__ b_hh) {
    __shared__ TileSmem sm;
    const int tid  = threadIdx.x;
    const int wid  = tid >> 5;
    const int lane = tid & 31;
    const int n0     = blockIdx.x * 64;
    const int m_base = blockIdx.y * 64;

    const int mw = wid >> 1;
    const int nw = wid & 1;
    const int m0 = mw * 16;
    const int a_row = m0 + (lane & 7) + 8 * ((lane >> 3) & 1);
    const int a_kh  = 8 * (lane >> 4);
    const int a_off = a_row * 24 + a_kh;
    const int b_lane = lane & 15;
    const int b_row0 = nw * 32 + (b_lane & 7);
    const int b_kh   = 8 * ((b_lane >> 3) & 1);

    const uint32_t sAhi = smem_u32(&sm.Ahi[0][0][0]);
    const uint32_t sAlo = smem_u32(&sm.Alo[0][0][0]);
    const uint32_t sBhi = smem_u32(&sm.Bhi[0][0][0]);
    const uint32_t sBlo = smem_u32(&sm.Blo[0][0][0]);

    float c[4][4] = {};

    for (int kc = 0; kc < 3; kc++) {
        #pragma unroll
        for (int i = 0; i < 2; i++) {
            int flat = tid + i * 256;
            int row = flat >> 3, q = flat & 7;
            size_t ga = (size_t)(m_base + row) * I_SZ + kc * 64 + q * 8;
            uint4 va_hi = *reinterpret_cast<const uint4*>(g_xhi + ga);
            uint4 va_lo = *reinterpret_cast<const uint4*>(g_xlo + ga);
            *reinterpret_cast<uint4*>(&sm.Ahi[q >> 1][row][(q & 1) * 8]) = va_hi;
            *reinterpret_cast<uint4*>(&sm.Alo[q >> 1][row][(q & 1) * 8]) = va_lo;
            size_t gb = (size_t)(n0 + row) * I_SZ + kc * 64 + q * 8;
            uint4 vb_hi = *reinterpret_cast<const uint4*>(g_wihi + gb);
            uint4 vb_lo = *reinterpret_cast<const uint4*>(g_wilo + gb);
            *reinterpret_cast<uint4*>(&sm.Bhi[q >> 1][row][(q & 1) * 8]) = vb_hi;
            *reinterpret_cast<uint4*>(&sm.Blo[q >> 1][row][(q & 1) * 8]) = vb_lo;
        }
        __syncthreads();
        #pragma unroll
        for (int ks = 0; ks < 4; ks++) {
            const uint32_t plane = (uint32_t)ks * 3072;
            uint32_t ahi[4], alo[4];
            ldsm_x4(ahi, sAhi + plane + a_off * 2);
            ldsm_x4(alo, sAlo + plane + a_off * 2);
            #pragma unroll
            for (int g4 = 0; g4 < 4; g4++) {
                uint32_t bhi[2], blo[2];
                uint32_t boff = plane + ((b_row0 + g4 * 8) * 24 + b_kh) * 2;
                ldsm_x2(bhi, sBhi + boff);
                ldsm_x2(blo, sBlo + boff);
                mma16816(c[g4], ahi, bhi);
                mma16816(c[g4], ahi, blo);
                mma16816(c[g4], alo, bhi);
            }
        }
        __syncthreads();
    }

    // fragments -> Cx
    {
        const int g  = lane >> 2;
        const int tq = lane & 3;
        #pragma unroll
        for (int g4 = 0; g4 < 4; g4++) {
            int n = nw * 32 + g4 * 8 + 2 * tq;
            sm.Cx[m0 + g][n]         = c[g4][0];
            sm.Cx[m0 + g][n + 1]     = c[g4][1];
            sm.Cx[m0 + g + 8][n]     = c[g4][2];
            sm.Cx[m0 + g + 8][n + 1] = c[g4][3];
        }
    }
    __syncthreads();

    // epilogue: thread owns row m = tid>>2, 16 consecutive cols
    const int m  = tid >> 2;
    const int cg = tid & 3;
    const int gm = m_base + m;
    const int b  = gm >> 9, tt = gm & 511;
    float* dst = g_xg + ((size_t)tt * B_SZ + b) * G4 + n0 + cg * 16;
    #pragma unroll
    for (int u4 = 0; u4 < 4; u4++) {
        float4 v;
        int nl = cg * 16 + u4 * 4;
        int n  = n0 + nl;
        v.x = sm.Cx[m][nl + 0] + b_ih[n + 0] + b_hh[n + 0];
        v.y = sm.Cx[m][nl + 1] + b_ih[n + 1] + b_hh[n + 1];
        v.z = sm.Cx[m][nl + 2] + b_ih[n + 2] + b_hh[n + 2];
        v.w = sm.Cx[m][nl + 3] + b_ih[n + 3] + b_hh[n + 3];
        *reinterpret_cast<float4*>(dst + u4 * 4) = v;
    }
}

// ---------------------------------------------------------------------------
// Kernel 2: one LSTM timestep, split-bf16 HMMA with cp.async 4-stage pipeline.
// Grid (32, 4), 256 thr. Tile M=64 batch x N=64 (gate*16+jj). K=512, 8 chunks.
// Dynamic smem: 4 stages x 48KB = 192KB. Cx epilogue aliases stage 0.
// ---------------------------------------------------------------------------
#define STAGE_BYTES 49152

__global__ void __launch_bounds__(256, 1)
step_mma_kernel(const float* __restrict__ c0,
                const float* __restrict__ W_out,
                float* __restrict__ out,
                int t) {
    extern __shared__ uint8_t dynsmem[];
    const uint32_t dyn = smem_u32(dynsmem);
    const int tid  = threadIdx.x;
    const int wid  = tid >> 5;
    const int lane = tid & 31;
    const int j0     = blockIdx.x * 16;
    const int m_base = blockIdx.y * 64;

    const int pb = (t + 1) & 1;
    const int cb = t & 1;
    const __nv_bfloat16* hhi = g_hhi[pb];
    const __nv_bfloat16* hlo = g_hlo[pb];

    const int mw = wid >> 1;
    const int nw = wid & 1;
    const int m0 = mw * 16;
    const int a_row = m0 + (lane & 7) + 8 * ((lane >> 3) & 1);
    const int a_kh  = 8 * (lane >> 4);
    const uint32_t a_off2 = (uint32_t)(a_row * 24 + a_kh) * 2;
    const int b_lane = lane & 15;
    const int b_row0 = nw * 32 + (b_lane & 7);
    const int b_kh   = 8 * ((b_lane >> 3) & 1);

    // per-thread transfer coords (2 x 16B per array per chunk)
    const int row0 = tid >> 3, q0 = tid & 7;
    const int row1 = (tid + 256) >> 3, q1 = (tid + 256) & 7;

    auto issue_chunk = [&](int kc) {
        const uint32_t sb = dyn + (uint32_t)(kc & 3) * STAGE_BYTES;
        #pragma unroll
        for (int i = 0; i < 2; i++) {
            const int row = i ? row1 : row0;
            const int q   = i ? q1   : q0;
            const uint32_t soff = (uint32_t)((q >> 1) * 3072 + row * 48 + (q & 1) * 16);
            size_t ga = (size_t)(m_base + row) * H_SZ + kc * 64 + q * 8;
            CP_ASYNC16(sb + soff,         hhi + ga);
            CP_ASYNC16(sb + 12288 + soff, hlo + ga);
            const int gate = row >> 4, jj = row & 15;
            size_t gb = (size_t)(gate * H_SZ + j0 + jj) * H_SZ + kc * 64 + q * 8;
            CP_ASYNC16(sb + 24576 + soff, g_whi + gb);
            CP_ASYNC16(sb + 36864 + soff, g_wlo + gb);
        }
        CP_COMMIT();
    };

    float c[4][4] = {};

    issue_chunk(0);
    issue_chunk(1);
    for (int kc = 0; kc < 8; kc++) {
        if (kc + 2 < 8) issue_chunk(kc + 2);
        if (kc < 6)       asm volatile("cp.async.wait_group 2;" ::: "memory");
        else if (kc == 6) asm volatile("cp.async.wait_group 1;" ::: "memory");
        else              asm volatile("cp.async.wait_group 0;" ::: "memory");
        __syncthreads();

        const uint32_t sb = dyn + (uint32_t)(kc & 3) * STAGE_BYTES;
        #pragma unroll
        for (int ks = 0; ks < 4; ks++) {
            const uint32_t plane = sb + (uint32_t)ks * 3072;
            uint32_t ahi[4], alo[4];
            ldsm_x4(ahi, plane + a_off2);
            ldsm_x4(alo, plane + 12288 + a_off2);
            #pragma unroll
            for (int g4 = 0; g4 < 4; g4++) {
                uint32_t bhi[2], blo[2];
                uint32_t boff = plane + ((b_row0 + g4 * 8) * 24 + b_kh) * 2;
                ldsm_x2(bhi, boff + 24576);
                ldsm_x2(blo, boff + 36864);
                mma16816(c[g4], ahi, bhi);
                mma16816(c[g4], ahi, blo);
                mma16816(c[g4], alo, bhi);
            }
        }
    }

    // fragments -> Cx (aliases stage 0, last consumed at kc=4: safe)
    float (*Cx)[65] = reinterpret_cast<float (*)[65]>(dynsmem);
    {
        const int g  = lane >> 2;
        const int tq = lane & 3;
        #pragma unroll
        for (int g4 = 0; g4 < 4; g4++) {
            int n = nw * 32 + g4 * 8 + 2 * tq;
            Cx[m0 + g][n]         = c[g4][0];
            Cx[m0 + g][n + 1]     = c[g4][1];
            Cx[m0 + g + 8][n]     = c[g4][2];
            Cx[m0 + g + 8][n + 1] = c[g4][3];
        }
    }
    __syncthreads();

    // epilogue: thread owns (m = tid>>2, 4 j's)
    const int m  = tid >> 2;
    const int jg = tid & 3;
    const int b  = m_base + m;
    const float* xg_t = g_xg + (size_t)t * B_SZ * G4 + (size_t)b * G4;
    const float* cin  = (t == 0) ? (c0 + (size_t)b * H_SZ) : (g_c + (size_t)b * H_SZ);
    float s = 0.f;
    uint32_t hi_pack[2], lo_pack[2];
    #pragma unroll
    for (int u = 0; u < 4; u++) {
        const int jj = jg * 4 + u;
        const int j  = j0 + jj;
        float gi = Cx[m][0 * 16 + jj] + xg_t[0 * H_SZ + j];
        float gf = Cx[m][1 * 16 + jj] + xg_t[1 * H_SZ + j];
        float gg = Cx[m][2 * 16 + jj] + xg_t[2 * H_SZ + j];
        float go = Cx[m][3 * 16 + jj] + xg_t[3 * H_SZ + j];
        gi = 1.0f / (1.0f + __expf(-gi));
        gf = 1.0f / (1.0f + __expf(-gf));
        gg = tanhf(gg);
        go = 1.0f / (1.0f + __expf(-go));
        float cn = gf * cin[j] + gi * gg;
        g_c[(size_t)b * H_SZ + j] = cn;
        float hv = go * tanhf(cn);
        s += hv * W_out[j];
        __nv_bfloat16 hvi = __float2bfloat16(hv);
        __nv_bfloat16 hvl = __float2bfloat16(hv - __bfloat162float(hvi));
        uint32_t uhi = (uint32_t)__bfloat16_as_ushort(hvi);
        uint32_t ulo = (uint32_t)__bfloat16_as_ushort(hvl);
        if (u & 1) { hi_pack[u >> 1] |= uhi << 16; lo_pack[u >> 1] |= ulo << 16; }
        else       { hi_pack[u >> 1]  = uhi;       lo_pack[u >> 1]  = ulo; }
    }
    size_t ho = (size_t)b * H_SZ + j0 + jg * 4;
    *reinterpret_cast<uint2*>(&g_hhi[cb][ho]) = make_uint2(hi_pack[0], hi_pack[1]);
    *reinterpret_cast<uint2*>(&g_hlo[cb][ho]) = make_uint2(lo_pack[0], lo_pack[1]);

    s += __shfl_xor_sync(0xffffffffu, s, 1);
    s += __shfl_xor_sync(0xffffffffu, s, 2);
    if (jg == 0) atomicAdd(&out[(size_t)b * T_STEPS + t], s);
}

// ---------------------------------------------------------------------------
extern "C" void kernel_launch(void* const* d_in, const int* in_sizes, int n_in,
                              void* d_out, int out_size) {
    const float* obs   = (const float*)d_in[0];
    const float* act   = (const float*)d_in[1];
    const float* h0    = (const float*)d_in[2];
    const float* c0    = (const float*)d_in[3];
    const float* W_ih  = (const float*)d_in[4];
    const float* W_hh  = (const float*)d_in[5];
    const float* b_ih  = (const float*)d_in[6];
    const float* b_hh  = (const float*)d_in[7];
    const float* W_out = (const float*)d_in[8];
    const float* b_out = (const float*)d_in[9];
    float* out = (float*)d_out;

    cudaFuncSetAttribute(step_mma_kernel,
                         cudaFuncAttributeMaxDynamicSharedMemorySize, 4 * STAGE_BYTES);

    init_out_kernel<<<(B_SZ * T_STEPS + 255) / 256, 256>>>(out, b_out);
    split_w_kernel<<<(G4 * H_SZ + 255) / 256, 256>>>(W_hh);
    split_wih_kernel<<<(G4 * I_SZ + 255) / 256, 256>>>(W_ih);
    split_h0_kernel<<<(B_SZ * H_SZ + 255) / 256, 256>>>(h0);
    split_x_kernel<<<(int)(((size_t)MT * I_SZ + 255) / 256), 256>>>(obs, act);

    dim3 gxg(G4 / 64, MT / 64);
    xg_mma_kernel<<<gxg, 256>>>(b_ih, b_hh);

    dim3 gs(32, 4);
    for (int t = 0; t < T_STEPS; t++)
        step_mma_kernel<<<gs, 256, 4 * STAGE_BYTES>>>(c0, W_out, out, t);
}

// round 10
// speedup vs baseline: 2.5911x; 1.1884x over previous
#include <cuda_runtime.h>
#include <cuda_bf16.h>
#include <cstdint>
#include <cstddef>

#define T_STEPS 512
#define B_SZ    256
#define H_SZ    512
#define I_SZ    192
#define G4      2048   // 4*H
#define MT      131072 // B*T
#define NBLOCKS 128

// ---------------------------------------------------------------------------
// Scratch (allocation-free rule: __device__ globals)
// ---------------------------------------------------------------------------
__device__ float         g_xg[(size_t)T_STEPS * B_SZ * G4];  // [T][B][4H] fp32
__device__ __nv_bfloat16 g_hhi[2][B_SZ * H_SZ];
__device__ __nv_bfloat16 g_hlo[2][B_SZ * H_SZ];
__device__ float         g_c  [B_SZ * H_SZ];
__device__ __nv_bfloat16 g_whi[(size_t)G4 * H_SZ];           // W_hh split
__device__ __nv_bfloat16 g_wlo[(size_t)G4 * H_SZ];
__device__ __nv_bfloat16 g_xhi[(size_t)MT * I_SZ];           // concat(obs,act) split
__device__ __nv_bfloat16 g_xlo[(size_t)MT * I_SZ];
__device__ __nv_bfloat16 g_wihi[(size_t)G4 * I_SZ];          // W_ih split
__device__ __nv_bfloat16 g_wilo[(size_t)G4 * I_SZ];
__device__ unsigned      g_bar;                              // grid barrier counter

// ---------------------------------------------------------------------------
// Helpers (sm_80+ baseline instructions only — no 'a'-features)
// ---------------------------------------------------------------------------
__device__ __forceinline__ uint32_t smem_u32(const void* p) {
    uint32_t a;
    asm("{ .reg .u64 t; cvta.to.shared.u64 t, %1; cvt.u32.u64 %0, t; }" : "=r"(a) : "l"(p));
    return a;
}
__device__ __forceinline__ void ldsm_x4(uint32_t r[4], uint32_t addr) {
    asm volatile("ldmatrix.sync.aligned.m8n8.x4.shared.b16 {%0,%1,%2,%3}, [%4];"
                 : "=r"(r[0]), "=r"(r[1]), "=r"(r[2]), "=r"(r[3]) : "r"(addr));
}
__device__ __forceinline__ void ldsm_x2(uint32_t r[2], uint32_t addr) {
    asm volatile("ldmatrix.sync.aligned.m8n8.x2.shared.b16 {%0,%1}, [%2];"
                 : "=r"(r[0]), "=r"(r[1]) : "r"(addr));
}
__device__ __forceinline__ void mma16816(float c[4], const uint32_t a[4], const uint32_t b[2]) {
    asm volatile("mma.sync.aligned.m16n8k16.row.col.f32.bf16.bf16.f32 "
                 "{%0,%1,%2,%3}, {%4,%5,%6,%7}, {%8,%9}, {%0,%1,%2,%3};"
                 : "+f"(c[0]), "+f"(c[1]), "+f"(c[2]), "+f"(c[3])
                 : "r"(a[0]), "r"(a[1]), "r"(a[2]), "r"(a[3]), "r"(b[0]), "r"(b[1]));
}
#define CP_ASYNC16(saddr, gptr) \
    asm volatile("cp.async.cg.shared.global [%0], [%1], 16;" \
                 :: "r"(saddr), "l"((const void*)(gptr)))
#define CP_COMMIT() asm volatile("cp.async.commit_group;" ::: "memory")

// ---------------------------------------------------------------------------
// Kernel 0: seed output with bias + reset grid barrier
// ---------------------------------------------------------------------------
__global__ void init_out_kernel(float* __restrict__ out, const float* __restrict__ b_out) {
    int i = blockIdx.x * blockDim.x + threadIdx.x;
    if (i == 0) g_bar = 0u;
    if (i < B_SZ * T_STEPS) out[i] = b_out[0];
}

// ---------------------------------------------------------------------------
// Split kernels: fp32 -> bf16 hi + bf16 lo
// ---------------------------------------------------------------------------
__global__ void split_w_kernel(const float* __restrict__ W) {
    int i = blockIdx.x * blockDim.x + threadIdx.x;
    if (i < G4 * H_SZ) {
        float w = W[i];
        __nv_bfloat16 hi = __float2bfloat16(w);
        g_whi[i] = hi;
        g_wlo[i] = __float2bfloat16(w - __bfloat162float(hi));
    }
}
__global__ void split_wih_kernel(const float* __restrict__ W) {
    int i = blockIdx.x * blockDim.x + threadIdx.x;
    if (i < G4 * I_SZ) {
        float w = W[i];
        __nv_bfloat16 hi = __float2bfloat16(w);
        g_wihi[i] = hi;
        g_wilo[i] = __float2bfloat16(w - __bfloat162float(hi));
    }
}
__global__ void split_h0_kernel(const float* __restrict__ h0) {
    int i = blockIdx.x * blockDim.x + threadIdx.x;
    if (i < B_SZ * H_SZ) {
        float h = h0[i];
        __nv_bfloat16 hi = __float2bfloat16(h);
        g_hhi[1][i] = hi;   // t=0 reads buffer (0+1)&1 = 1
        g_hlo[1][i] = __float2bfloat16(h - __bfloat162float(hi));
    }
}
__global__ void split_x_kernel(const float* __restrict__ obs, const float* __restrict__ act) {
    size_t i = (size_t)blockIdx.x * blockDim.x + threadIdx.x;
    if (i >= (size_t)MT * I_SZ) return;
    int m = (int)(i / I_SZ), k = (int)(i % I_SZ);
    int b = m >> 9, t = m & 511;
    float v = (k < 128) ? obs[((size_t)(b * T_STEPS + t)) * 128 + k]
                        : act[((size_t)(b * T_STEPS + t)) * 64 + (k - 128)];
    __nv_bfloat16 hi = __float2bfloat16(v);
    g_xhi[i] = hi;
    g_xlo[i] = __float2bfloat16(v - __bfloat162float(hi));
}

// ---------------------------------------------------------------------------
// Kernel 1: xg GEMM via split-bf16 HMMA (verified R8). Tile 64x64, K=192.
// ---------------------------------------------------------------------------
struct __align__(16) TileSmem {
    union {
        struct {
            __nv_bfloat16 Ahi[4][64][24];
            __nv_bfloat16 Alo[4][64][24];
            __nv_bfloat16 Bhi[4][64][24];
            __nv_bfloat16 Blo[4][64][24];
        };
        float Cx[64][65];
    };
};

__global__ void __launch_bounds__(256)
xg_mma_kernel(const float* __restrict__ b_ih, const float* __restrict__ b_hh) {
    __shared__ TileSmem sm;
    const int tid  = threadIdx.x;
    const int wid  = tid >> 5;
    const int lane = tid & 31;
    const int n0     = blockIdx.x * 64;
    const int m_base = blockIdx.y * 64;

    const int mw = wid >> 1;
    const int nw = wid & 1;
    const int m0 = mw * 16;
    const int a_row = m0 + (lane & 7) + 8 * ((lane >> 3) & 1);
    const int a_kh  = 8 * (lane >> 4);
    const int a_off = a_row * 24 + a_kh;
    const int b_lane = lane & 15;
    const int b_row0 = nw * 32 + (b_lane & 7);
    const int b_kh   = 8 * ((b_lane >> 3) & 1);

    const uint32_t sAhi = smem_u32(&sm.Ahi[0][0][0]);
    const uint32_t sAlo = smem_u32(&sm.Alo[0][0][0]);
    const uint32_t sBhi = smem_u32(&sm.Bhi[0][0][0]);
    const uint32_t sBlo = smem_u32(&sm.Blo[0][0][0]);

    float c[4][4] = {};

    for (int kc = 0; kc < 3; kc++) {
        #pragma unroll
        for (int i = 0; i < 2; i++) {
            int flat = tid + i * 256;
            int row = flat >> 3, q = flat & 7;
            size_t ga = (size_t)(m_base + row) * I_SZ + kc * 64 + q * 8;
            uint4 va_hi = *reinterpret_cast<const uint4*>(g_xhi + ga);
            uint4 va_lo = *reinterpret_cast<const uint4*>(g_xlo + ga);
            *reinterpret_cast<uint4*>(&sm.Ahi[q >> 1][row][(q & 1) * 8]) = va_hi;
            *reinterpret_cast<uint4*>(&sm.Alo[q >> 1][row][(q & 1) * 8]) = va_lo;
            size_t gb = (size_t)(n0 + row) * I_SZ + kc * 64 + q * 8;
            uint4 vb_hi = *reinterpret_cast<const uint4*>(g_wihi + gb);
            uint4 vb_lo = *reinterpret_cast<const uint4*>(g_wilo + gb);
            *reinterpret_cast<uint4*>(&sm.Bhi[q >> 1][row][(q & 1) * 8]) = vb_hi;
            *reinterpret_cast<uint4*>(&sm.Blo[q >> 1][row][(q & 1) * 8]) = vb_lo;
        }
        __syncthreads();
        #pragma unroll
        for (int ks = 0; ks < 4; ks++) {
            const uint32_t plane = (uint32_t)ks * 3072;
            uint32_t ahi[4], alo[4];
            ldsm_x4(ahi, sAhi + plane + a_off * 2);
            ldsm_x4(alo, sAlo + plane + a_off * 2);
            #pragma unroll
            for (int g4 = 0; g4 < 4; g4++) {
                uint32_t bhi[2], blo[2];
                uint32_t boff = plane + ((b_row0 + g4 * 8) * 24 + b_kh) * 2;
                ldsm_x2(bhi, sBhi + boff);
                ldsm_x2(blo, sBlo + boff);
                mma16816(c[g4], ahi, bhi);
                mma16816(c[g4], ahi, blo);
                mma16816(c[g4], alo, bhi);
            }
        }
        __syncthreads();
    }

    {
        const int g  = lane >> 2;
        const int tq = lane & 3;
        #pragma unroll
        for (int g4 = 0; g4 < 4; g4++) {
            int n = nw * 32 + g4 * 8 + 2 * tq;
            sm.Cx[m0 + g][n]         = c[g4][0];
            sm.Cx[m0 + g][n + 1]     = c[g4][1];
            sm.Cx[m0 + g + 8][n]     = c[g4][2];
            sm.Cx[m0 + g + 8][n + 1] = c[g4][3];
        }
    }
    __syncthreads();

    const int m  = tid >> 2;
    const int cg = tid & 3;
    const int gm = m_base + m;
    const int b  = gm >> 9, tt = gm & 511;
    float* dst = g_xg + ((size_t)tt * B_SZ + b) * G4 + n0 + cg * 16;
    #pragma unroll
    for (int u4 = 0; u4 < 4; u4++) {
        float4 v;
        int nl = cg * 16 + u4 * 4;
        int n  = n0 + nl;
        v.x = sm.Cx[m][nl + 0] + b_ih[n + 0] + b_hh[n + 0];
        v.y = sm.Cx[m][nl + 1] + b_ih[n + 1] + b_hh[n + 1];
        v.z = sm.Cx[m][nl + 2] + b_ih[n + 2] + b_hh[n + 2];
        v.w = sm.Cx[m][nl + 3] + b_ih[n + 3] + b_hh[n + 3];
        *reinterpret_cast<float4*>(dst + u4 * 4) = v;
    }
}

// ---------------------------------------------------------------------------
// Kernel 2: PERSISTENT recurrence. Grid (32, 4) = 128 blocks, 256 thr.
// W_hh hi/lo resident in smem (128 KB, swizzled pitch-16, XOR bit4 per 4-row
// group => ldmatrix conflict-free; XOR folds to per-lane constant).
// Per step: h streamed via THREE-stage cp.async (prefetch distance 2 requires
// >=3 stages: chunk kc+2 lands in stage (kc+2)%3 != kc%3, last consumed at
// kc-1 and ordered by that iteration's trailing __syncthreads — the 2-stage
// version raced and was the R9 correctness bug).
// Software grid barrier between steps.
// Dynamic smem layout:
//   [0, 64K)      W hi   (byte = k16*2048 + ((row*32 + half*16) ^ swz(row)))
//   [64K, 128K)   W lo
//   [128K, +72K)  A stages 0..2: Ahi[4][64][24] (12288B) + Alo (12288B) each
//   Cx (64x65 f32) aliases stage 0 (used after all A consumed).
// ---------------------------------------------------------------------------
#define W_BYTES      65536
#define ASTAGE_OFF   131072
#define ASTAGE_BYTES 24576
#define SMEM_TOTAL_P (ASTAGE_OFF + 3 * ASTAGE_BYTES)

__global__ void __launch_bounds__(256, 1)
lstm_persist_kernel(const float* __restrict__ c0,
                    const float* __restrict__ W_out,
                    float* __restrict__ out) {
    extern __shared__ uint8_t dynsmem[];
    const uint32_t dyn = smem_u32(dynsmem);
    const int tid  = threadIdx.x;
    const int wid  = tid >> 5;
    const int lane = tid & 31;
    const int j0     = blockIdx.x * 16;
    const int m_base = blockIdx.y * 64;

    // ---- load resident W (once): 4096 16B-chunks per array ----
    for (int idx = tid; idx < 4096; idx += 256) {
        int k16 = idx >> 7;          // 0..31
        int rem = idx & 127;
        int row = rem >> 1;          // 0..63  (n = gate*16 + jj)
        int half = rem & 1;
        int gate = row >> 4, jj = row & 15;
        size_t g = (size_t)(gate * H_SZ + j0 + jj) * H_SZ + k16 * 16 + half * 8;
        uint32_t off = (uint32_t)(k16 * 2048 +
                       ((row * 32 + half * 16) ^ (((row >> 2) & 1) << 4)));
        *reinterpret_cast<uint4*>(dynsmem + off)           =
            *reinterpret_cast<const uint4*>(g_whi + g);
        *reinterpret_cast<uint4*>(dynsmem + W_BYTES + off) =
            *reinterpret_cast<const uint4*>(g_wlo + g);
    }
    __syncthreads();

    // ---- per-lane constants ----
    const int mw = wid >> 1;
    const int nw = wid & 1;
    const int m0 = mw * 16;
    const int a_row = m0 + (lane & 7) + 8 * ((lane >> 3) & 1);
    const int a_kh  = 8 * (lane >> 4);
    const uint32_t a_off2 = (uint32_t)(a_row * 24 + a_kh) * 2;
    const int b_lane = lane & 15;
    const int b_row0 = nw * 32 + (b_lane & 7);
    // swizzled half-offset: constant per lane (row>>2 parity invariant in g4)
    const uint32_t hb2 = (uint32_t)((16 * ((b_lane >> 3) & 1)) ^
                                    (((b_row0 >> 2) & 1) << 4));
    const uint32_t wHiB = dyn + (uint32_t)(b_row0 * 32) + hb2;
    const uint32_t wLoB = wHiB + W_BYTES;

    // A-transfer coords (2 x 16B per array per chunk per thread)
    const int row0 = tid >> 3, q0 = tid & 7;
    const int row1 = (tid + 256) >> 3, q1 = (tid + 256) & 7;

    // epilogue constants
    const int em = tid >> 2;        // batch row within tile
    const int jg = tid & 3;
    const int eb = m_base + em;     // global batch
    float (*Cx)[65] = reinterpret_cast<float (*)[65]>(dynsmem + ASTAGE_OFF);
    volatile unsigned* vbar = &g_bar;

    for (int t = 0; t < T_STEPS; t++) {
        const __nv_bfloat16* hhi = g_hhi[(t + 1) & 1];
        const __nv_bfloat16* hlo = g_hlo[(t + 1) & 1];
        const int cb = t & 1;

        auto issue_chunk = [&](int kc) {
            const uint32_t sb = dyn + ASTAGE_OFF + (uint32_t)(kc % 3) * ASTAGE_BYTES;
            #pragma unroll
            for (int i = 0; i < 2; i++) {
                const int row = i ? row1 : row0;
                const int q   = i ? q1   : q0;
                const uint32_t soff = (uint32_t)((q >> 1) * 3072 + row * 48 + (q & 1) * 16);
                size_t ga = (size_t)(m_base + row) * H_SZ + kc * 64 + q * 8;
                CP_ASYNC16(sb + soff,         hhi + ga);
                CP_ASYNC16(sb + 12288 + soff, hlo + ga);
            }
            CP_COMMIT();
        };

        issue_chunk(0);
        issue_chunk(1);

        // prefetch xg for this thread's epilogue (hides DRAM latency behind MMAs)
        float xg_r[4][4];
        {
            const float* xg_t = g_xg + (size_t)t * B_SZ * G4 + (size_t)eb * G4;
            #pragma unroll
            for (int g = 0; g < 4; g++)
                *reinterpret_cast<float4*>(xg_r[g]) =
                    *reinterpret_cast<const float4*>(xg_t + g * H_SZ + j0 + jg * 4);
        }

        float c[4][4] = {};

        for (int kc = 0; kc < 8; kc++) {
            if (kc + 2 < 8) issue_chunk(kc + 2);
            if (kc < 6)       asm volatile("cp.async.wait_group 2;" ::: "memory");
            else if (kc == 6) asm volatile("cp.async.wait_group 1;" ::: "memory");
            else              asm volatile("cp.async.wait_group 0;" ::: "memory");
            __syncthreads();

            const uint32_t sb = dyn + ASTAGE_OFF + (uint32_t)(kc % 3) * ASTAGE_BYTES;
            #pragma unroll
            for (int ks = 0; ks < 4; ks++) {
                const uint32_t aplane = sb + (uint32_t)ks * 3072;
                const uint32_t wplane = (uint32_t)(kc * 4 + ks) * 2048;
                uint32_t ahi[4], alo[4];
                ldsm_x4(ahi, aplane + a_off2);
                ldsm_x4(alo, aplane + 12288 + a_off2);
                #pragma unroll
                for (int g4 = 0; g4 < 4; g4++) {
                    uint32_t bhi[2], blo[2];
                    ldsm_x2(bhi, wHiB + wplane + (uint32_t)(g4 * 256));
                    ldsm_x2(blo, wLoB + wplane + (uint32_t)(g4 * 256));
                    mma16816(c[g4], ahi, bhi);
                    mma16816(c[g4], ahi, blo);
                    mma16816(c[g4], alo, bhi);
                }
            }
            __syncthreads();
        }

        // fragments -> Cx (aliases stage 0; chunk 6 (stage 0) consumed at kc=6,
        // trailing sync above orders it)
        {
            const int g  = lane >> 2;
            const int tq = lane & 3;
            #pragma unroll
            for (int g4 = 0; g4 < 4; g4++) {
                int n = nw * 32 + g4 * 8 + 2 * tq;
                Cx[m0 + g][n]         = c[g4][0];
                Cx[m0 + g][n + 1]     = c[g4][1];
                Cx[m0 + g + 8][n]     = c[g4][2];
                Cx[m0 + g + 8][n + 1] = c[g4][3];
            }
        }
        __syncthreads();

        // epilogue: thread owns (em, 4 j's)
        const float* cin = (t == 0) ? (c0 + (size_t)eb * H_SZ) : (g_c + (size_t)eb * H_SZ);
        float s = 0.f;
        uint32_t hi_pack[2], lo_pack[2];
        #pragma unroll
        for (int u = 0; u < 4; u++) {
            const int jj = jg * 4 + u;
            const int j  = j0 + jj;
            float gi = Cx[em][0 * 16 + jj] + xg_r[0][u];
            float gf = Cx[em][1 * 16 + jj] + xg_r[1][u];
            float gg = Cx[em][2 * 16 + jj] + xg_r[2][u];
            float go = Cx[em][3 * 16 + jj] + xg_r[3][u];
            gi = 1.0f / (1.0f + __expf(-gi));
            gf = 1.0f / (1.0f + __expf(-gf));
            gg = tanhf(gg);
            go = 1.0f / (1.0f + __expf(-go));
            float cn = gf * cin[j] + gi * gg;
            g_c[(size_t)eb * H_SZ + j] = cn;
            float hv = go * tanhf(cn);
            s += hv * W_out[j];
            __nv_bfloat16 hvi = __float2bfloat16(hv);
            __nv_bfloat16 hvl = __float2bfloat16(hv - __bfloat162float(hvi));
            uint32_t uhi = (uint32_t)__bfloat16_as_ushort(hvi);
            uint32_t ulo = (uint32_t)__bfloat16_as_ushort(hvl);
            if (u & 1) { hi_pack[u >> 1] |= uhi << 16; lo_pack[u >> 1] |= ulo << 16; }
            else       { hi_pack[u >> 1]  = uhi;       lo_pack[u >> 1]  = ulo; }
        }
        size_t ho = (size_t)eb * H_SZ + j0 + jg * 4;
        *reinterpret_cast<uint2*>(&g_hhi[cb][ho]) = make_uint2(hi_pack[0], hi_pack[1]);
        *reinterpret_cast<uint2*>(&g_hlo[cb][ho]) = make_uint2(lo_pack[0], lo_pack[1]);

        s += __shfl_xor_sync(0xffffffffu, s, 1);
        s += __shfl_xor_sync(0xffffffffu, s, 2);
        if (jg == 0) atomicAdd(&out[(size_t)eb * T_STEPS + t], s);

        // ---- grid barrier (release -> arrive -> spin -> acquire) ----
        __threadfence();
        __syncthreads();
        if (tid == 0) {
            atomicAdd(&g_bar, 1u);
            const unsigned target = (unsigned)NBLOCKS * (unsigned)(t + 1);
            while (*vbar < target) { }
            __threadfence();
        }
        __syncthreads();
    }
}

// ---------------------------------------------------------------------------
extern "C" void kernel_launch(void* const* d_in, const int* in_sizes, int n_in,
                              void* d_out, int out_size) {
    const float* obs   = (const float*)d_in[0];
    const float* act   = (const float*)d_in[1];
    const float* h0    = (const float*)d_in[2];
    const float* c0    = (const float*)d_in[3];
    const float* W_ih  = (const float*)d_in[4];
    const float* W_hh  = (const float*)d_in[5];
    const float* b_ih  = (const float*)d_in[6];
    const float* b_hh  = (const float*)d_in[7];
    const float* W_out = (const float*)d_in[8];
    const float* b_out = (const float*)d_in[9];
    float* out = (float*)d_out;

    cudaFuncSetAttribute(lstm_persist_kernel,
                         cudaFuncAttributeMaxDynamicSharedMemorySize, SMEM_TOTAL_P);

    init_out_kernel<<<(B_SZ * T_STEPS + 255) / 256, 256>>>(out, b_out);
    split_w_kernel<<<(G4 * H_SZ + 255) / 256, 256>>>(W_hh);
    split_wih_kernel<<<(G4 * I_SZ + 255) / 256, 256>>>(W_ih);
    split_h0_kernel<<<(B_SZ * H_SZ + 255) / 256, 256>>>(h0);
    split_x_kernel<<<(int)(((size_t)MT * I_SZ + 255) / 256), 256>>>(obs, act);

    dim3 gxg(G4 / 64, MT / 64);
    xg_mma_kernel<<<gxg, 256>>>(b_ih, b_hh);

    dim3 gp(32, 4);
    lstm_persist_kernel<<<gp, 256, SMEM_TOTAL_P>>>(c0, W_out, out);
}

// round 11
// speedup vs baseline: 2.7281x; 1.0529x over previous
#include <cuda_runtime.h>
#include <cuda_bf16.h>
#include <cstdint>
#include <cstddef>

#define T_STEPS 512
#define B_SZ    256
#define H_SZ    512
#define I_SZ    192
#define G4      2048   // 4*H
#define MT      131072 // B*T
#define GROUP_BLOCKS 32

// ---------------------------------------------------------------------------
// Scratch (allocation-free rule: __device__ globals)
// ---------------------------------------------------------------------------
__device__ float         g_xg[(size_t)T_STEPS * B_SZ * G4];  // [T][B][4H] fp32
__device__ __nv_bfloat16 g_hhi[2][B_SZ * H_SZ];
__device__ __nv_bfloat16 g_hlo[2][B_SZ * H_SZ];
__device__ float         g_c  [B_SZ * H_SZ];
__device__ __nv_bfloat16 g_whi[(size_t)G4 * H_SZ];           // W_hh split
__device__ __nv_bfloat16 g_wlo[(size_t)G4 * H_SZ];
__device__ __nv_bfloat16 g_xhi[(size_t)MT * I_SZ];           // concat(obs,act) split
__device__ __nv_bfloat16 g_xlo[(size_t)MT * I_SZ];
__device__ __nv_bfloat16 g_wihi[(size_t)G4 * I_SZ];          // W_ih split
__device__ __nv_bfloat16 g_wilo[(size_t)G4 * I_SZ];
__device__ unsigned      g_bars[4][32];                      // per-batch-tile barriers

// ---------------------------------------------------------------------------
// Helpers (sm_80+ baseline instructions only — no 'a'-features)
// ---------------------------------------------------------------------------
__device__ __forceinline__ uint32_t smem_u32(const void* p) {
    uint32_t a;
    asm("{ .reg .u64 t; cvta.to.shared.u64 t, %1; cvt.u32.u64 %0, t; }" : "=r"(a) : "l"(p));
    return a;
}
__device__ __forceinline__ void ldsm_x4(uint32_t r[4], uint32_t addr) {
    asm volatile("ldmatrix.sync.aligned.m8n8.x4.shared.b16 {%0,%1,%2,%3}, [%4];"
                 : "=r"(r[0]), "=r"(r[1]), "=r"(r[2]), "=r"(r[3]) : "r"(addr));
}
__device__ __forceinline__ void ldsm_x2(uint32_t r[2], uint32_t addr) {
    asm volatile("ldmatrix.sync.aligned.m8n8.x2.shared.b16 {%0,%1}, [%2];"
                 : "=r"(r[0]), "=r"(r[1]) : "r"(addr));
}
__device__ __forceinline__ void mma16816(float c[4], const uint32_t a[4], const uint32_t b[2]) {
    asm volatile("mma.sync.aligned.m16n8k16.row.col.f32.bf16.bf16.f32 "
                 "{%0,%1,%2,%3}, {%4,%5,%6,%7}, {%8,%9}, {%0,%1,%2,%3};"
                 : "+f"(c[0]), "+f"(c[1]), "+f"(c[2]), "+f"(c[3])
                 : "r"(a[0]), "r"(a[1]), "r"(a[2]), "r"(a[3]), "r"(b[0]), "r"(b[1]));
}
#define CP_ASYNC16(saddr, gptr) \
    asm volatile("cp.async.cg.shared.global [%0], [%1], 16;" \
                 :: "r"(saddr), "l"((const void*)(gptr)))
#define CP_COMMIT() asm volatile("cp.async.commit_group;" ::: "memory")

// Fast activations: MUFU.EX2 + MUFU.RCP paths regardless of harness fast-math.
__device__ __forceinline__ float fsigmoid(float x) {
    return __fdividef(1.0f, 1.0f + __expf(-x));
}
__device__ __forceinline__ float ftanh_fast(float x) {
    // 1 - 2/(1+e^{2x}); saturates correctly: x->+inf => exp=inf => 1; x->-inf => -1.
    return 1.0f - __fdividef(2.0f, 1.0f + __expf(2.0f * x));
}

// ---------------------------------------------------------------------------
// Kernel 0: seed output with bias + reset group barriers
// ---------------------------------------------------------------------------
__global__ void init_out_kernel(float* __restrict__ out, const float* __restrict__ b_out) {
    int i = blockIdx.x * blockDim.x + threadIdx.x;
    if (i < 128) ((unsigned*)g_bars)[i] = 0u;
    if (i < B_SZ * T_STEPS) out[i] = b_out[0];
}

// ---------------------------------------------------------------------------
// Split kernels: fp32 -> bf16 hi + bf16 lo
// ---------------------------------------------------------------------------
__global__ void split_w_kernel(const float* __restrict__ W) {
    int i = blockIdx.x * blockDim.x + threadIdx.x;
    if (i < G4 * H_SZ) {
        float w = W[i];
        __nv_bfloat16 hi = __float2bfloat16(w);
        g_whi[i] = hi;
        g_wlo[i] = __float2bfloat16(w - __bfloat162float(hi));
    }
}
__global__ void split_wih_kernel(const float* __restrict__ W) {
    int i = blockIdx.x * blockDim.x + threadIdx.x;
    if (i < G4 * I_SZ) {
        float w = W[i];
        __nv_bfloat16 hi = __float2bfloat16(w);
        g_wihi[i] = hi;
        g_wilo[i] = __float2bfloat16(w - __bfloat162float(hi));
    }
}
__global__ void split_h0_kernel(const float* __restrict__ h0) {
    int i = blockIdx.x * blockDim.x + threadIdx.x;
    if (i < B_SZ * H_SZ) {
        float h = h0[i];
        __nv_bfloat16 hi = __float2bfloat16(h);
        g_hhi[1][i] = hi;   // t=0 reads buffer (0+1)&1 = 1
        g_hlo[1][i] = __float2bfloat16(h - __bfloat162float(hi));
    }
}
__global__ void split_x_kernel(const float* __restrict__ obs, const float* __restrict__ act) {
    size_t i = (size_t)blockIdx.x * blockDim.x + threadIdx.x;
    if (i >= (size_t)MT * I_SZ) return;
    int m = (int)(i / I_SZ), k = (int)(i % I_SZ);
    int b = m >> 9, t = m & 511;
    float v = (k < 128) ? obs[((size_t)(b * T_STEPS + t)) * 128 + k]
                        : act[((size_t)(b * T_STEPS + t)) * 64 + (k - 128)];
    __nv_bfloat16 hi = __float2bfloat16(v);
    g_xhi[i] = hi;
    g_xlo[i] = __float2bfloat16(v - __bfloat162float(hi));
}

// ---------------------------------------------------------------------------
// Kernel 1: xg GEMM via split-bf16 HMMA (verified R8). Tile 64x64, K=192.
// ---------------------------------------------------------------------------
struct __align__(16) TileSmem {
    union {
        struct {
            __nv_bfloat16 Ahi[4][64][24];
            __nv_bfloat16 Alo[4][64][24];
            __nv_bfloat16 Bhi[4][64][24];
            __nv_bfloat16 Blo[4][64][24];
        };
        float Cx[64][65];
    };
};

__global__ void __launch_bounds__(256)
xg_mma_kernel(const float* __restrict__ b_ih, const float* __restrict__ b_hh) {
    __shared__ TileSmem sm;
    const int tid  = threadIdx.x;
    const int wid  = tid >> 5;
    const int lane = tid & 31;
    const int n0     = blockIdx.x * 64;
    const int m_base = blockIdx.y * 64;

    const int mw = wid >> 1;
    const int nw = wid & 1;
    const int m0 = mw * 16;
    const int a_row = m0 + (lane & 7) + 8 * ((lane >> 3) & 1);
    const int a_kh  = 8 * (lane >> 4);
    const int a_off = a_row * 24 + a_kh;
    const int b_lane = lane & 15;
    const int b_row0 = nw * 32 + (b_lane & 7);
    const int b_kh   = 8 * ((b_lane >> 3) & 1);

    const uint32_t sAhi = smem_u32(&sm.Ahi[0][0][0]);
    const uint32_t sAlo = smem_u32(&sm.Alo[0][0][0]);
    const uint32_t sBhi = smem_u32(&sm.Bhi[0][0][0]);
    const uint32_t sBlo = smem_u32(&sm.Blo[0][0][0]);

    float c[4][4] = {};

    for (int kc = 0; kc < 3; kc++) {
        #pragma unroll
        for (int i = 0; i < 2; i++) {
            int flat = tid + i * 256;
            int row = flat >> 3, q = flat & 7;
            size_t ga = (size_t)(m_base + row) * I_SZ + kc * 64 + q * 8;
            uint4 va_hi = *reinterpret_cast<const uint4*>(g_xhi + ga);
            uint4 va_lo = *reinterpret_cast<const uint4*>(g_xlo + ga);
            *reinterpret_cast<uint4*>(&sm.Ahi[q >> 1][row][(q & 1) * 8]) = va_hi;
            *reinterpret_cast<uint4*>(&sm.Alo[q >> 1][row][(q & 1) * 8]) = va_lo;
            size_t gb = (size_t)(n0 + row) * I_SZ + kc * 64 + q * 8;
            uint4 vb_hi = *reinterpret_cast<const uint4*>(g_wihi + gb);
            uint4 vb_lo = *reinterpret_cast<const uint4*>(g_wilo + gb);
            *reinterpret_cast<uint4*>(&sm.Bhi[q >> 1][row][(q & 1) * 8]) = vb_hi;
            *reinterpret_cast<uint4*>(&sm.Blo[q >> 1][row][(q & 1) * 8]) = vb_lo;
        }
        __syncthreads();
        #pragma unroll
        for (int ks = 0; ks < 4; ks++) {
            const uint32_t plane = (uint32_t)ks * 3072;
            uint32_t ahi[4], alo[4];
            ldsm_x4(ahi, sAhi + plane + a_off * 2);
            ldsm_x4(alo, sAlo + plane + a_off * 2);
            #pragma unroll
            for (int g4 = 0; g4 < 4; g4++) {
                uint32_t bhi[2], blo[2];
                uint32_t boff = plane + ((b_row0 + g4 * 8) * 24 + b_kh) * 2;
                ldsm_x2(bhi, sBhi + boff);
                ldsm_x2(blo, sBlo + boff);
                mma16816(c[g4], ahi, bhi);
                mma16816(c[g4], ahi, blo);
                mma16816(c[g4], alo, bhi);
            }
        }
        __syncthreads();
    }

    {
        const int g  = lane >> 2;
        const int tq = lane & 3;
        #pragma unroll
        for (int g4 = 0; g4 < 4; g4++) {
            int n = nw * 32 + g4 * 8 + 2 * tq;
            sm.Cx[m0 + g][n]         = c[g4][0];
            sm.Cx[m0 + g][n + 1]     = c[g4][1];
            sm.Cx[m0 + g + 8][n]     = c[g4][2];
            sm.Cx[m0 + g + 8][n + 1] = c[g4][3];
        }
    }
    __syncthreads();

    const int m  = tid >> 2;
    const int cg = tid & 3;
    const int gm = m_base + m;
    const int b  = gm >> 9, tt = gm & 511;
    float* dst = g_xg + ((size_t)tt * B_SZ + b) * G4 + n0 + cg * 16;
    #pragma unroll
    for (int u4 = 0; u4 < 4; u4++) {
        float4 v;
        int nl = cg * 16 + u4 * 4;
        int n  = n0 + nl;
        v.x = sm.Cx[m][nl + 0] + b_ih[n + 0] + b_hh[n + 0];
        v.y = sm.Cx[m][nl + 1] + b_ih[n + 1] + b_hh[n + 1];
        v.z = sm.Cx[m][nl + 2] + b_ih[n + 2] + b_hh[n + 2];
        v.w = sm.Cx[m][nl + 3] + b_ih[n + 3] + b_hh[n + 3];
        *reinterpret_cast<float4*>(dst + u4 * 4) = v;
    }
}

// ---------------------------------------------------------------------------
// Kernel 2: PERSISTENT recurrence. Grid (32, 4) = 128 blocks, 256 thr.
// W_hh hi/lo resident in smem (128 KB). h streamed via FOUR-stage cp.async,
// prefetch distance 2, SINGLE __syncthreads per chunk (stage kc+2 mod 4 cannot
// collide with reads of chunk kc-2: those reads precede the leading sync of
// kc-1, which the issuing thread has passed).
// Synchronization is per-batch-tile: 4 independent 32-block barriers.
// Dynamic smem: [0,64K) W hi | [64K,128K) W lo | [128K,+96K) A stages 0..3.
// Cx (64x65 f32) aliases stage 0.
// ---------------------------------------------------------------------------
#define W_BYTES      65536
#define ASTAGE_OFF   131072
#define ASTAGE_BYTES 24576
#define SMEM_TOTAL_P (ASTAGE_OFF + 4 * ASTAGE_BYTES)

__global__ void __launch_bounds__(256, 1)
lstm_persist_kernel(const float* __restrict__ c0,
                    const float* __restrict__ W_out,
                    float* __restrict__ out) {
    extern __shared__ uint8_t dynsmem[];
    const uint32_t dyn = smem_u32(dynsmem);
    const int tid  = threadIdx.x;
    const int wid  = tid >> 5;
    const int lane = tid & 31;
    const int j0     = blockIdx.x * 16;
    const int by     = blockIdx.y;
    const int m_base = by * 64;

    // ---- load resident W (once) ----
    for (int idx = tid; idx < 4096; idx += 256) {
        int k16 = idx >> 7;
        int rem = idx & 127;
        int row = rem >> 1;
        int half = rem & 1;
        int gate = row >> 4, jj = row & 15;
        size_t g = (size_t)(gate * H_SZ + j0 + jj) * H_SZ + k16 * 16 + half * 8;
        uint32_t off = (uint32_t)(k16 * 2048 +
                       ((row * 32 + half * 16) ^ (((row >> 2) & 1) << 4)));
        *reinterpret_cast<uint4*>(dynsmem + off)           =
            *reinterpret_cast<const uint4*>(g_whi + g);
        *reinterpret_cast<uint4*>(dynsmem + W_BYTES + off) =
            *reinterpret_cast<const uint4*>(g_wlo + g);
    }
    __syncthreads();

    // ---- per-lane constants ----
    const int mw = wid >> 1;
    const int nw = wid & 1;
    const int m0 = mw * 16;
    const int a_row = m0 + (lane & 7) + 8 * ((lane >> 3) & 1);
    const int a_kh  = 8 * (lane >> 4);
    const uint32_t a_off2 = (uint32_t)(a_row * 24 + a_kh) * 2;
    const int b_lane = lane & 15;
    const int b_row0 = nw * 32 + (b_lane & 7);
    const uint32_t hb2 = (uint32_t)((16 * ((b_lane >> 3) & 1)) ^
                                    (((b_row0 >> 2) & 1) << 4));
    const uint32_t wHiB = dyn + (uint32_t)(b_row0 * 32) + hb2;
    const uint32_t wLoB = wHiB + W_BYTES;

    const int row0 = tid >> 3, q0 = tid & 7;
    const int row1 = (tid + 256) >> 3, q1 = (tid + 256) & 7;

    const int em = tid >> 2;
    const int jg = tid & 3;
    const int eb = m_base + em;
    float (*Cx)[65] = reinterpret_cast<float (*)[65]>(dynsmem + ASTAGE_OFF);
    volatile unsigned* vbar = &g_bars[by][0];

    // prologue: prefetch xg for t=0
    float xg_r[4][4];
    {
        const float* xg_t = g_xg + (size_t)eb * G4;
        #pragma unroll
        for (int g = 0; g < 4; g++)
            *reinterpret_cast<float4*>(xg_r[g]) =
                *reinterpret_cast<const float4*>(xg_t + g * H_SZ + j0 + jg * 4);
    }

    for (int t = 0; t < T_STEPS; t++) {
        // ---- wait for group h availability (t>0) ----
        if (t > 0) {
            if (tid == 0) {
                const unsigned target = (unsigned)GROUP_BLOCKS * (unsigned)t;
                while (*vbar < target) { }
                __threadfence();
            }
            __syncthreads();
        }

        const __nv_bfloat16* hhi = g_hhi[(t + 1) & 1];
        const __nv_bfloat16* hlo = g_hlo[(t + 1) & 1];
        const int cb = t & 1;

        auto issue_chunk = [&](int kc) {
            const uint32_t sb = dyn + ASTAGE_OFF + (uint32_t)(kc & 3) * ASTAGE_BYTES;
            #pragma unroll
            for (int i = 0; i < 2; i++) {
                const int row = i ? row1 : row0;
                const int q   = i ? q1   : q0;
                const uint32_t soff = (uint32_t)((q >> 1) * 3072 + row * 48 + (q & 1) * 16);
                size_t ga = (size_t)(m_base + row) * H_SZ + kc * 64 + q * 8;
                CP_ASYNC16(sb + soff,         hhi + ga);
                CP_ASYNC16(sb + 12288 + soff, hlo + ga);
            }
            CP_COMMIT();
        };

        issue_chunk(0);
        issue_chunk(1);

        float c[4][4] = {};

        for (int kc = 0; kc < 8; kc++) {
            if (kc + 2 < 8) issue_chunk(kc + 2);
            if (kc < 6)       asm volatile("cp.async.wait_group 2;" ::: "memory");
            else if (kc == 6) asm volatile("cp.async.wait_group 1;" ::: "memory");
            else              asm volatile("cp.async.wait_group 0;" ::: "memory");
            __syncthreads();   // single sync per chunk (4-stage safety)

            const uint32_t sb = dyn + ASTAGE_OFF + (uint32_t)(kc & 3) * ASTAGE_BYTES;
            #pragma unroll
            for (int ks = 0; ks < 4; ks++) {
                const uint32_t aplane = sb + (uint32_t)ks * 3072;
                const uint32_t wplane = (uint32_t)(kc * 4 + ks) * 2048;
                uint32_t ahi[4], alo[4];
                ldsm_x4(ahi, aplane + a_off2);
                ldsm_x4(alo, aplane + 12288 + a_off2);
                #pragma unroll
                for (int g4 = 0; g4 < 4; g4++) {
                    uint32_t bhi[2], blo[2];
                    ldsm_x2(bhi, wHiB + wplane + (uint32_t)(g4 * 256));
                    ldsm_x2(blo, wLoB + wplane + (uint32_t)(g4 * 256));
                    mma16816(c[g4], ahi, bhi);
                    mma16816(c[g4], ahi, blo);
                    mma16816(c[g4], alo, bhi);
                }
            }
        }
        __syncthreads();  // all MMA reads complete before Cx overwrites stage 0

        {
            const int g  = lane >> 2;
            const int tq = lane & 3;
            #pragma unroll
            for (int g4 = 0; g4 < 4; g4++) {
                int n = nw * 32 + g4 * 8 + 2 * tq;
                Cx[m0 + g][n]         = c[g4][0];
                Cx[m0 + g][n + 1]     = c[g4][1];
                Cx[m0 + g + 8][n]     = c[g4][2];
                Cx[m0 + g + 8][n + 1] = c[g4][3];
            }
        }
        __syncthreads();

        // ---- epilogue: thread owns (em, 4 j's) ----
        const float* cin = (t == 0) ? (c0 + (size_t)eb * H_SZ) : (g_c + (size_t)eb * H_SZ);
        float s = 0.f;
        uint32_t hi_pack[2], lo_pack[2];
        #pragma unroll
        for (int u = 0; u < 4; u++) {
            const int jj = jg * 4 + u;
            const int j  = j0 + jj;
            float gi = Cx[em][0 * 16 + jj] + xg_r[0][u];
            float gf = Cx[em][1 * 16 + jj] + xg_r[1][u];
            float gg = Cx[em][2 * 16 + jj] + xg_r[2][u];
            float go = Cx[em][3 * 16 + jj] + xg_r[3][u];
            gi = fsigmoid(gi);
            gf = fsigmoid(gf);
            gg = ftanh_fast(gg);
            go = fsigmoid(go);
            float cn = gf * cin[j] + gi * gg;
            g_c[(size_t)eb * H_SZ + j] = cn;
            float hv = go * ftanh_fast(cn);
            s += hv * W_out[j];
            __nv_bfloat16 hvi = __float2bfloat16(hv);
            __nv_bfloat16 hvl = __float2bfloat16(hv - __bfloat162float(hvi));
            uint32_t uhi = (uint32_t)__bfloat16_as_ushort(hvi);
            uint32_t ulo = (uint32_t)__bfloat16_as_ushort(hvl);
            if (u & 1) { hi_pack[u >> 1] |= uhi << 16; lo_pack[u >> 1] |= ulo << 16; }
            else       { hi_pack[u >> 1]  = uhi;       lo_pack[u >> 1]  = ulo; }
        }
        size_t ho = (size_t)eb * H_SZ + j0 + jg * 4;
        *reinterpret_cast<uint2*>(&g_hhi[cb][ho]) = make_uint2(hi_pack[0], hi_pack[1]);
        *reinterpret_cast<uint2*>(&g_hlo[cb][ho]) = make_uint2(lo_pack[0], lo_pack[1]);

        s += __shfl_xor_sync(0xffffffffu, s, 1);
        s += __shfl_xor_sync(0xffffffffu, s, 2);
        if (jg == 0) atomicAdd(&out[(size_t)eb * T_STEPS + t], s);

        // ---- arrive (release) then prefetch next xg during peers' arrival ----
        __threadfence();
        __syncthreads();
        if (tid == 0) atomicAdd(&g_bars[by][0], 1u);
        if (t + 1 < T_STEPS) {
            const float* xg_t = g_xg + (size_t)(t + 1) * B_SZ * G4 + (size_t)eb * G4;
            #pragma unroll
            for (int g = 0; g < 4; g++)
                *reinterpret_cast<float4*>(xg_r[g]) =
                    *reinterpret_cast<const float4*>(xg_t + g * H_SZ + j0 + jg * 4);
        }
    }
}

// ---------------------------------------------------------------------------
extern "C" void kernel_launch(void* const* d_in, const int* in_sizes, int n_in,
                              void* d_out, int out_size) {
    const float* obs   = (const float*)d_in[0];
    const float* act   = (const float*)d_in[1];
    const float* h0    = (const float*)d_in[2];
    const float* c0    = (const float*)d_in[3];
    const float* W_ih  = (const float*)d_in[4];
    const float* W_hh  = (const float*)d_in[5];
    const float* b_ih  = (const float*)d_in[6];
    const float* b_hh  = (const float*)d_in[7];
    const float* W_out = (const float*)d_in[8];
    const float* b_out = (const float*)d_in[9];
    float* out = (float*)d_out;

    cudaFuncSetAttribute(lstm_persist_kernel,
                         cudaFuncAttributeMaxDynamicSharedMemorySize, SMEM_TOTAL_P);

    init_out_kernel<<<(B_SZ * T_STEPS + 255) / 256, 256>>>(out, b_out);
    split_w_kernel<<<(G4 * H_SZ + 255) / 256, 256>>>(W_hh);
    split_wih_kernel<<<(G4 * I_SZ + 255) / 256, 256>>>(W_ih);
    split_h0_kernel<<<(B_SZ * H_SZ + 255) / 256, 256>>>(h0);
    split_x_kernel<<<(int)(((size_t)MT * I_SZ + 255) / 256), 256>>>(obs, act);

    dim3 gxg(G4 / 64, MT / 64);
    xg_mma_kernel<<<gxg, 256>>>(b_ih, b_hh);

    dim3 gp(32, 4);
    lstm_persist_kernel<<<gp, 256, SMEM_TOTAL_P>>>(c0, W_out, out);
}

// round 12
// speedup vs baseline: 3.2532x; 1.1925x over previous
#include <cuda_runtime.h>
#include <cuda_fp16.h>
#include <cstdint>
#include <cstddef>

#define T_STEPS 512
#define B_SZ    256
#define H_SZ    512
#define I_SZ    192
#define G4      2048   // 4*H
#define MT      131072 // B*T
#define GROUP_BLOCKS 32

// ---------------------------------------------------------------------------
// Scratch (allocation-free rule: __device__ globals)
// ---------------------------------------------------------------------------
__device__ float    g_xg[(size_t)T_STEPS * B_SZ * G4];  // [T][B][4H] fp32
__device__ __half   g_hhi[2][B_SZ * H_SZ];              // h hi (fp16), double-buffered
__device__ __half   g_hlo[2][B_SZ * H_SZ];              // h lo (fp16)
__device__ float    g_c  [B_SZ * H_SZ];
__device__ __half   g_wh [(size_t)G4 * H_SZ];           // fp16(W_hh)
__device__ __half   g_xhi[(size_t)MT * I_SZ];           // x hi (fp16)
__device__ __half   g_xlo[(size_t)MT * I_SZ];           // x lo (fp16)
__device__ __half   g_wih[(size_t)G4 * I_SZ];           // fp16(W_ih)
__device__ unsigned g_bars[4][32];                      // per-batch-tile barriers

// ---------------------------------------------------------------------------
// Helpers (sm_80+ baseline instructions only — no 'a'-features)
// ---------------------------------------------------------------------------
__device__ __forceinline__ uint32_t smem_u32(const void* p) {
    uint32_t a;
    asm("{ .reg .u64 t; cvta.to.shared.u64 t, %1; cvt.u32.u64 %0, t; }" : "=r"(a) : "l"(p));
    return a;
}
__device__ __forceinline__ void ldsm_x4(uint32_t r[4], uint32_t addr) {
    asm volatile("ldmatrix.sync.aligned.m8n8.x4.shared.b16 {%0,%1,%2,%3}, [%4];"
                 : "=r"(r[0]), "=r"(r[1]), "=r"(r[2]), "=r"(r[3]) : "r"(addr));
}
__device__ __forceinline__ void ldsm_x2(uint32_t r[2], uint32_t addr) {
    asm volatile("ldmatrix.sync.aligned.m8n8.x2.shared.b16 {%0,%1}, [%2];"
                 : "=r"(r[0]), "=r"(r[1]) : "r"(addr));
}
__device__ __forceinline__ void mma16816(float c[4], const uint32_t a[4], const uint32_t b[2]) {
    asm volatile("mma.sync.aligned.m16n8k16.row.col.f32.f16.f16.f32 "
                 "{%0,%1,%2,%3}, {%4,%5,%6,%7}, {%8,%9}, {%0,%1,%2,%3};"
                 : "+f"(c[0]), "+f"(c[1]), "+f"(c[2]), "+f"(c[3])
                 : "r"(a[0]), "r"(a[1]), "r"(a[2]), "r"(a[3]), "r"(b[0]), "r"(b[1]));
}
#define CP_ASYNC16(saddr, gptr) \
    asm volatile("cp.async.cg.shared.global [%0], [%1], 16;" \
                 :: "r"(saddr), "l"((const void*)(gptr)))
#define CP_COMMIT() asm volatile("cp.async.commit_group;" ::: "memory")

__device__ __forceinline__ float fsigmoid(float x) {
    return __fdividef(1.0f, 1.0f + __expf(-x));
}
__device__ __forceinline__ float ftanh_fast(float x) {
    return 1.0f - __fdividef(2.0f, 1.0f + __expf(2.0f * x));
}

// ---------------------------------------------------------------------------
// Kernel 0: seed output with bias + reset group barriers
// ---------------------------------------------------------------------------
__global__ void init_out_kernel(float* __restrict__ out, const float* __restrict__ b_out) {
    int i = blockIdx.x * blockDim.x + threadIdx.x;
    if (i < 128) ((unsigned*)g_bars)[i] = 0u;
    if (i < B_SZ * T_STEPS) out[i] = b_out[0];
}

// ---------------------------------------------------------------------------
// Split / convert kernels
// ---------------------------------------------------------------------------
__global__ void conv_w_kernel(const float* __restrict__ W) {
    int i = blockIdx.x * blockDim.x + threadIdx.x;
    if (i < G4 * H_SZ) g_wh[i] = __float2half(W[i]);
}
__global__ void conv_wih_kernel(const float* __restrict__ W) {
    int i = blockIdx.x * blockDim.x + threadIdx.x;
    if (i < G4 * I_SZ) g_wih[i] = __float2half(W[i]);
}
__global__ void split_h0_kernel(const float* __restrict__ h0) {
    int i = blockIdx.x * blockDim.x + threadIdx.x;
    if (i < B_SZ * H_SZ) {
        float h = h0[i];
        __half hi = __float2half(h);
        g_hhi[1][i] = hi;   // t=0 reads buffer (0+1)&1 = 1
        g_hlo[1][i] = __float2half(h - __half2float(hi));
    }
}
__global__ void split_x_kernel(const float* __restrict__ obs, const float* __restrict__ act) {
    size_t i = (size_t)blockIdx.x * blockDim.x + threadIdx.x;
    if (i >= (size_t)MT * I_SZ) return;
    int m = (int)(i / I_SZ), k = (int)(i % I_SZ);
    int b = m >> 9, t = m & 511;
    float v = (k < 128) ? obs[((size_t)(b * T_STEPS + t)) * 128 + k]
                        : act[((size_t)(b * T_STEPS + t)) * 64 + (k - 128)];
    __half hi = __float2half(v);
    g_xhi[i] = hi;
    g_xlo[i] = __float2half(v - __half2float(hi));
}

// ---------------------------------------------------------------------------
// Kernel 1: xg GEMM, 2-term fp16 split HMMA. Tile 64x64, K=192 (3 chunks).
// ---------------------------------------------------------------------------
struct __align__(16) TileSmem {
    union {
        struct {
            __half Ahi[4][64][24];   // [k16][m][16 valid + 8 pad]
            __half Alo[4][64][24];
            __half Bh [4][64][24];
        };
        float Cx[64][65];
    };
};

__global__ void __launch_bounds__(256)
xg_mma_kernel(const float* __restrict__ b_ih, const float* __restrict__ b_hh) {
    __shared__ TileSmem sm;
    const int tid  = threadIdx.x;
    const int wid  = tid >> 5;
    const int lane = tid & 31;
    const int n0     = blockIdx.x * 64;
    const int m_base = blockIdx.y * 64;

    const int mw = wid >> 1;
    const int nw = wid & 1;
    const int m0 = mw * 16;
    const int a_row = m0 + (lane & 7) + 8 * ((lane >> 3) & 1);
    const int a_kh  = 8 * (lane >> 4);
    const int a_off = a_row * 24 + a_kh;
    const int b_lane = lane & 15;
    const int b_row0 = nw * 32 + (b_lane & 7);
    const int b_kh   = 8 * ((b_lane >> 3) & 1);

    const uint32_t sAhi = smem_u32(&sm.Ahi[0][0][0]);
    const uint32_t sAlo = smem_u32(&sm.Alo[0][0][0]);
    const uint32_t sBh  = smem_u32(&sm.Bh [0][0][0]);

    float c[4][4] = {};

    for (int kc = 0; kc < 3; kc++) {
        #pragma unroll
        for (int i = 0; i < 2; i++) {
            int flat = tid + i * 256;
            int row = flat >> 3, q = flat & 7;
            size_t ga = (size_t)(m_base + row) * I_SZ + kc * 64 + q * 8;
            uint4 va_hi = *reinterpret_cast<const uint4*>(g_xhi + ga);
            uint4 va_lo = *reinterpret_cast<const uint4*>(g_xlo + ga);
            *reinterpret_cast<uint4*>(&sm.Ahi[q >> 1][row][(q & 1) * 8]) = va_hi;
            *reinterpret_cast<uint4*>(&sm.Alo[q >> 1][row][(q & 1) * 8]) = va_lo;
            size_t gb = (size_t)(n0 + row) * I_SZ + kc * 64 + q * 8;
            uint4 vb = *reinterpret_cast<const uint4*>(g_wih + gb);
            *reinterpret_cast<uint4*>(&sm.Bh[q >> 1][row][(q & 1) * 8]) = vb;
        }
        __syncthreads();
        #pragma unroll
        for (int ks = 0; ks < 4; ks++) {
            const uint32_t plane = (uint32_t)ks * 3072;
            uint32_t ahi[4], alo[4];
            ldsm_x4(ahi, sAhi + plane + a_off * 2);
            ldsm_x4(alo, sAlo + plane + a_off * 2);
            #pragma unroll
            for (int g4 = 0; g4 < 4; g4++) {
                uint32_t bh[2];
                uint32_t boff = plane + ((b_row0 + g4 * 8) * 24 + b_kh) * 2;
                ldsm_x2(bh, sBh + boff);
                mma16816(c[g4], ahi, bh);
                mma16816(c[g4], alo, bh);
            }
        }
        __syncthreads();
    }

    {
        const int g  = lane >> 2;
        const int tq = lane & 3;
        #pragma unroll
        for (int g4 = 0; g4 < 4; g4++) {
            int n = nw * 32 + g4 * 8 + 2 * tq;
            sm.Cx[m0 + g][n]         = c[g4][0];
            sm.Cx[m0 + g][n + 1]     = c[g4][1];
            sm.Cx[m0 + g + 8][n]     = c[g4][2];
            sm.Cx[m0 + g + 8][n + 1] = c[g4][3];
        }
    }
    __syncthreads();

    const int m  = tid >> 2;
    const int cg = tid & 3;
    const int gm = m_base + m;
    const int b  = gm >> 9, tt = gm & 511;
    float* dst = g_xg + ((size_t)tt * B_SZ + b) * G4 + n0 + cg * 16;
    #pragma unroll
    for (int u4 = 0; u4 < 4; u4++) {
        float4 v;
        int nl = cg * 16 + u4 * 4;
        int n  = n0 + nl;
        v.x = sm.Cx[m][nl + 0] + b_ih[n + 0] + b_hh[n + 0];
        v.y = sm.Cx[m][nl + 1] + b_ih[n + 1] + b_hh[n + 1];
        v.z = sm.Cx[m][nl + 2] + b_ih[n + 2] + b_hh[n + 2];
        v.w = sm.Cx[m][nl + 3] + b_ih[n + 3] + b_hh[n + 3];
        *reinterpret_cast<float4*>(dst + u4 * 4) = v;
    }
}

// ---------------------------------------------------------------------------
// Kernel 2: PERSISTENT recurrence. Grid (32, 4) = 128 blocks, 256 thr.
// fp16(W_hh) resident in smem (64 KB, pitch-32B rows, XOR-bit4 per 4-row group
// => ldmatrix conflict-free). h = exact fp16 hi/lo split; 2 MMA terms.
// h streamed via 4-stage cp.async, prefetch distance 2, 1 sync per chunk.
// Per-batch-tile 32-block barriers.
// Dynamic smem: [0,64K) W | [64K,+96K) A stages 0..3 (24 KB each).
// Cx (64x65 f32) aliases stage 0.
// ---------------------------------------------------------------------------
#define W_BYTES      65536
#define ASTAGE_OFF   65536
#define ASTAGE_BYTES 24576
#define SMEM_TOTAL_P (ASTAGE_OFF + 4 * ASTAGE_BYTES)

__global__ void __launch_bounds__(256, 1)
lstm_persist_kernel(const float* __restrict__ c0,
                    const float* __restrict__ W_out,
                    float* __restrict__ out) {
    extern __shared__ uint8_t dynsmem[];
    const uint32_t dyn = smem_u32(dynsmem);
    const int tid  = threadIdx.x;
    const int wid  = tid >> 5;
    const int lane = tid & 31;
    const int j0     = blockIdx.x * 16;
    const int by     = blockIdx.y;
    const int m_base = by * 64;

    // ---- load resident fp16 W (once): 4096 16B-chunks ----
    for (int idx = tid; idx < 4096; idx += 256) {
        int k16 = idx >> 7;
        int rem = idx & 127;
        int row = rem >> 1;
        int half = rem & 1;
        int gate = row >> 4, jj = row & 15;
        size_t g = (size_t)(gate * H_SZ + j0 + jj) * H_SZ + k16 * 16 + half * 8;
        uint32_t off = (uint32_t)(k16 * 2048 +
                       ((row * 32 + half * 16) ^ (((row >> 2) & 1) << 4)));
        *reinterpret_cast<uint4*>(dynsmem + off) =
            *reinterpret_cast<const uint4*>(g_wh + g);
    }
    __syncthreads();

    // ---- per-lane constants ----
    const int mw = wid >> 1;
    const int nw = wid & 1;
    const int m0 = mw * 16;
    const int a_row = m0 + (lane & 7) + 8 * ((lane >> 3) & 1);
    const int a_kh  = 8 * (lane >> 4);
    const uint32_t a_off2 = (uint32_t)(a_row * 24 + a_kh) * 2;
    const int b_lane = lane & 15;
    const int b_row0 = nw * 32 + (b_lane & 7);
    const uint32_t hb2 = (uint32_t)((16 * ((b_lane >> 3) & 1)) ^
                                    (((b_row0 >> 2) & 1) << 4));
    const uint32_t wB = dyn + (uint32_t)(b_row0 * 32) + hb2;

    const int row0 = tid >> 3, q0 = tid & 7;
    const int row1 = (tid + 256) >> 3, q1 = (tid + 256) & 7;

    const int em = tid >> 2;
    const int jg = tid & 3;
    const int eb = m_base + em;
    float (*Cx)[65] = reinterpret_cast<float (*)[65]>(dynsmem + ASTAGE_OFF);
    volatile unsigned* vbar = &g_bars[by][0];

    // prologue: prefetch xg for t=0
    float xg_r[4][4];
    {
        const float* xg_t = g_xg + (size_t)eb * G4;
        #pragma unroll
        for (int g = 0; g < 4; g++)
            *reinterpret_cast<float4*>(xg_r[g]) =
                *reinterpret_cast<const float4*>(xg_t + g * H_SZ + j0 + jg * 4);
    }

    for (int t = 0; t < T_STEPS; t++) {
        if (t > 0) {
            if (tid == 0) {
                const unsigned target = (unsigned)GROUP_BLOCKS * (unsigned)t;
                while (*vbar < target) { }
                __threadfence();
            }
            __syncthreads();
        }

        const __half* hhi = g_hhi[(t + 1) & 1];
        const __half* hlo = g_hlo[(t + 1) & 1];
        const int cb = t & 1;

        auto issue_chunk = [&](int kc) {
            const uint32_t sb = dyn + ASTAGE_OFF + (uint32_t)(kc & 3) * ASTAGE_BYTES;
            #pragma unroll
            for (int i = 0; i < 2; i++) {
                const int row = i ? row1 : row0;
                const int q   = i ? q1   : q0;
                const uint32_t soff = (uint32_t)((q >> 1) * 3072 + row * 48 + (q & 1) * 16);
                size_t ga = (size_t)(m_base + row) * H_SZ + kc * 64 + q * 8;
                CP_ASYNC16(sb + soff,         hhi + ga);
                CP_ASYNC16(sb + 12288 + soff, hlo + ga);
            }
            CP_COMMIT();
        };

        issue_chunk(0);
        issue_chunk(1);

        float c[4][4] = {};

        for (int kc = 0; kc < 8; kc++) {
            if (kc + 2 < 8) issue_chunk(kc + 2);
            if (kc < 6)       asm volatile("cp.async.wait_group 2;" ::: "memory");
            else if (kc == 6) asm volatile("cp.async.wait_group 1;" ::: "memory");
            else              asm volatile("cp.async.wait_group 0;" ::: "memory");
            __syncthreads();   // single sync per chunk (4-stage safety)

            const uint32_t sb = dyn + ASTAGE_OFF + (uint32_t)(kc & 3) * ASTAGE_BYTES;
            #pragma unroll
            for (int ks = 0; ks < 4; ks++) {
                const uint32_t aplane = sb + (uint32_t)ks * 3072;
                const uint32_t wplane = (uint32_t)(kc * 4 + ks) * 2048;
                uint32_t ahi[4], alo[4];
                ldsm_x4(ahi, aplane + a_off2);
                ldsm_x4(alo, aplane + 12288 + a_off2);
                #pragma unroll
                for (int g4 = 0; g4 < 4; g4++) {
                    uint32_t bh[2];
                    ldsm_x2(bh, wB + wplane + (uint32_t)(g4 * 256));
                    mma16816(c[g4], ahi, bh);
                    mma16816(c[g4], alo, bh);
                }
            }
        }
        __syncthreads();  // MMA reads complete before Cx overwrites stage 0

        {
            const int g  = lane >> 2;
            const int tq = lane & 3;
            #pragma unroll
            for (int g4 = 0; g4 < 4; g4++) {
                int n = nw * 32 + g4 * 8 + 2 * tq;
                Cx[m0 + g][n]         = c[g4][0];
                Cx[m0 + g][n + 1]     = c[g4][1];
                Cx[m0 + g + 8][n]     = c[g4][2];
                Cx[m0 + g + 8][n + 1] = c[g4][3];
            }
        }
        __syncthreads();

        // ---- epilogue: thread owns (em, 4 j's) ----
        const float* cin = (t == 0) ? (c0 + (size_t)eb * H_SZ) : (g_c + (size_t)eb * H_SZ);
        float s = 0.f;
        uint32_t hi_pack[2], lo_pack[2];
        #pragma unroll
        for (int u = 0; u < 4; u++) {
            const int jj = jg * 4 + u;
            const int j  = j0 + jj;
            float gi = Cx[em][0 * 16 + jj] + xg_r[0][u];
            float gf = Cx[em][1 * 16 + jj] + xg_r[1][u];
            float gg = Cx[em][2 * 16 + jj] + xg_r[2][u];
            float go = Cx[em][3 * 16 + jj] + xg_r[3][u];
            gi = fsigmoid(gi);
            gf = fsigmoid(gf);
            gg = ftanh_fast(gg);
            go = fsigmoid(go);
            float cn = gf * cin[j] + gi * gg;
            g_c[(size_t)eb * H_SZ + j] = cn;
            float hv = go * ftanh_fast(cn);
            s += hv * W_out[j];
            __half hvi = __float2half(hv);
            __half hvl = __float2half(hv - __half2float(hvi));
            uint32_t uhi = (uint32_t)__half_as_ushort(hvi);
            uint32_t ulo = (uint32_t)__half_as_ushort(hvl);
            if (u & 1) { hi_pack[u >> 1] |= uhi << 16; lo_pack[u >> 1] |= ulo << 16; }
            else       { hi_pack[u >> 1]  = uhi;       lo_pack[u >> 1]  = ulo; }
        }
        size_t ho = (size_t)eb * H_SZ + j0 + jg * 4;
        *reinterpret_cast<uint2*>(&g_hhi[cb][ho]) = make_uint2(hi_pack[0], hi_pack[1]);
        *reinterpret_cast<uint2*>(&g_hlo[cb][ho]) = make_uint2(lo_pack[0], lo_pack[1]);

        s += __shfl_xor_sync(0xffffffffu, s, 1);
        s += __shfl_xor_sync(0xffffffffu, s, 2);
        if (jg == 0) atomicAdd(&out[(size_t)eb * T_STEPS + t], s);

        // ---- arrive (release), then prefetch next xg during peers' arrival ----
        __threadfence();
        __syncthreads();
        if (tid == 0) atomicAdd(&g_bars[by][0], 1u);
        if (t + 1 < T_STEPS) {
            const float* xg_t = g_xg + (size_t)(t + 1) * B_SZ * G4 + (size_t)eb * G4;
            #pragma unroll
            for (int g = 0; g < 4; g++)
                *reinterpret_cast<float4*>(xg_r[g]) =
                    *reinterpret_cast<const float4*>(xg_t + g * H_SZ + j0 + jg * 4);
        }
    }
}

// ---------------------------------------------------------------------------
extern "C" void kernel_launch(void* const* d_in, const int* in_sizes, int n_in,
                              void* d_out, int out_size) {
    const float* obs   = (const float*)d_in[0];
    const float* act   = (const float*)d_in[1];
    const float* h0    = (const float*)d_in[2];
    const float* c0    = (const float*)d_in[3];
    const float* W_ih  = (const float*)d_in[4];
    const float* W_hh  = (const float*)d_in[5];
    const float* b_ih  = (const float*)d_in[6];
    const float* b_hh  = (const float*)d_in[7];
    const float* W_out = (const float*)d_in[8];
    const float* b_out = (const float*)d_in[9];
    float* out = (float*)d_out;

    cudaFuncSetAttribute(lstm_persist_kernel,
                         cudaFuncAttributeMaxDynamicSharedMemorySize, SMEM_TOTAL_P);

    init_out_kernel<<<(B_SZ * T_STEPS + 255) / 256, 256>>>(out, b_out);
    conv_w_kernel<<<(G4 * H_SZ + 255) / 256, 256>>>(W_hh);
    conv_wih_kernel<<<(G4 * I_SZ + 255) / 256, 256>>>(W_ih);
    split_h0_kernel<<<(B_SZ * H_SZ + 255) / 256, 256>>>(h0);
    split_x_kernel<<<(int)(((size_t)MT * I_SZ + 255) / 256), 256>>>(obs, act);

    dim3 gxg(G4 / 64, MT / 64);
    xg_mma_kernel<<<gxg, 256>>>(b_ih, b_hh);

    dim3 gp(32, 4);
    lstm_persist_kernel<<<gp, 256, SMEM_TOTAL_P>>>(c0, W_out, out);
}